// round 3
// baseline (speedup 1.0000x reference)
#include <cuda_runtime.h>

#define NN 50000
#define NE 500000
#define DD 128

// ---------------- device scratch (static: no allocations allowed) ----------------
__device__ float g_srcP[(size_t)NN * DD];   // src @ W_s2e^T
__device__ float g_tgtP[(size_t)NN * DD];   // tgt @ W_t2e^T
__device__ float g_agg [(size_t)NN * DD];   // segment_sum(edge_out)
__device__ float g_WtS[DD * DD];            // W_s2e transposed: Wt[k][j] = W[j][k]
__device__ float g_WtT[DD * DD];
__device__ float g_WtE[DD * DD];
__device__ float g_WtN[2 * DD * DD];        // [W_e2t^T ; W_t2t^T] stacked along k

typedef unsigned long long u64;

__device__ __forceinline__ u64 pack2(float lo, float hi) {
    u64 r; asm("mov.b64 %0,{%1,%2};" : "=l"(r) : "f"(lo), "f"(hi)); return r;
}
__device__ __forceinline__ float2 unpack2(u64 v) {
    float2 f; asm("mov.b64 {%0,%1},%2;" : "=f"(f.x), "=f"(f.y) : "l"(v)); return f;
}
// packed f32x2 FMA (sm_100+): 2 FMAs per instruction -> 2x fp32 throughput
__device__ __forceinline__ u64 ffma2(u64 a, u64 b, u64 c) {
    u64 d; asm("fma.rn.f32x2 %0,%1,%2,%3;" : "=l"(d) : "l"(a), "l"(b), "l"(c)); return d;
}
__device__ __forceinline__ float silu(float x) { return x * (1.0f / (1.0f + __expf(-x))); }

// ---------------- K0: transpose weights into scratch ----------------
__global__ void prep_kernel(const float* __restrict__ Ws2e, const float* __restrict__ Wt2e,
                            const float* __restrict__ We2e, const float* __restrict__ We2t,
                            const float* __restrict__ Wt2t) {
    int i = blockIdx.x * blockDim.x + threadIdx.x;
    if (i < DD * DD) {
        int k = i >> 7, j = i & 127;
        int s = j * DD + k;
        g_WtS[i] = Ws2e[s];
        g_WtT[i] = Wt2e[s];
        g_WtE[i] = We2e[s];
        g_WtN[i] = We2t[s];
        g_WtN[DD * DD + i] = Wt2t[s];
    }
}

// ---------------- Kz: zero the aggregation buffer ----------------
__global__ void zero_agg_kernel() {
    const size_t n = (size_t)NN * DD / 4;
    float4 z = make_float4(0.f, 0.f, 0.f, 0.f);
    for (size_t i = blockIdx.x * (size_t)blockDim.x + threadIdx.x; i < n;
         i += (size_t)gridDim.x * blockDim.x)
        ((float4*)g_agg)[i] = z;
}

// ---------------- shared GEMM microkernel ----------------
// Block = 256 threads (8 warps). Warp w owns rows [w*2*EPL, (w+1)*2*EPL).
// Lane mapping: colg = lane&15 -> 8 output cols at j0=colg*8; eg = lane>>4 -> row parity.
// Thread accumulates EPL edges x 8 cols as EPL x 4 packed f32x2.
template <int EPL, int KK, int PITCH>
__device__ __forceinline__ void gemm_tile(const float* __restrict__ xs,
                                          const float* __restrict__ wt,
                                          int tid, u64 (&acc)[EPL][4]) {
    const int lane = tid & 31;
    const int j0 = (lane & 15) << 3;
    const int eb = (tid >> 5) * (2 * EPL) + (lane >> 4);
#pragma unroll
    for (int i = 0; i < EPL; i++) {
#pragma unroll
        for (int c = 0; c < 4; c++) acc[i][c] = 0ull;
    }
#pragma unroll 2
    for (int k = 0; k < KK; k += 2) {
        float4 wa = *(const float4*)(wt + k * DD + j0);
        float4 wb = *(const float4*)(wt + k * DD + j0 + 4);
        float4 wc = *(const float4*)(wt + (k + 1) * DD + j0);
        float4 wd = *(const float4*)(wt + (k + 1) * DD + j0 + 4);
        u64 w0[4] = { pack2(wa.x, wa.y), pack2(wa.z, wa.w), pack2(wb.x, wb.y), pack2(wb.z, wb.w) };
        u64 w1[4] = { pack2(wc.x, wc.y), pack2(wc.z, wc.w), pack2(wd.x, wd.y), pack2(wd.z, wd.w) };
#pragma unroll
        for (int i = 0; i < EPL; i++) {
            float2 xv = *(const float2*)(xs + (eb + 2 * i) * PITCH + k);
            u64 xa = pack2(xv.x, xv.x);
            u64 xb = pack2(xv.y, xv.y);
#pragma unroll
            for (int c = 0; c < 4; c++) {
                acc[i][c] = ffma2(xa, w0[c], acc[i][c]);
                acc[i][c] = ffma2(xb, w1[c], acc[i][c]);
            }
        }
    }
}

__device__ __forceinline__ void load_w(float* ws, const float* __restrict__ gw,
                                       int nfloats, int tid, int nthr) {
    const float4* s = (const float4*)gw;
    float4* d = (float4*)ws;
    for (int i = tid; i < (nfloats >> 2); i += nthr) d[i] = s[i];
}

template <int TM, int PITCH>
__device__ __forceinline__ void load_x(float* xs, const float* __restrict__ g,
                                       int base, int M, int tid, int nthr) {
    for (int i = tid; i < TM * 32; i += nthr) {
        int r = i >> 5, c = i & 31;
        float4 v = make_float4(0.f, 0.f, 0.f, 0.f);
        int row = base + r;
        if (row < M) v = __ldg((const float4*)(g + (size_t)row * DD) + c);
        *(float4*)(xs + r * PITCH + 4 * c) = v;
    }
}

// ---------------- K1: node projections srcP = src@W_s2e^T, tgtP = tgt@W_t2e^T ----------------
__global__ void __launch_bounds__(256, 1)
node_proj_kernel(const float* __restrict__ src, const float* __restrict__ tgt) {
    extern __shared__ float sm[];
    float* ws = sm;               // 128x128
    float* xs = sm + DD * DD;     // 128 x pitch 132
    const int tid = threadIdx.x;
    const int base = blockIdx.x * 128;
    const float* X; const float* W; float* O;
    if (blockIdx.y == 0) { X = src; W = g_WtS; O = g_srcP; }
    else                 { X = tgt; W = g_WtT; O = g_tgtP; }
    load_w(ws, W, DD * DD, tid, 256);
    load_x<128, 132>(xs, X, base, NN, tid, 256);
    __syncthreads();
    u64 acc[8][4];
    gemm_tile<8, 128, 132>(xs, ws, tid, acc);
    const int lane = tid & 31;
    const int j0 = (lane & 15) << 3;
    const int eb = (tid >> 5) * 16 + (lane >> 4);
#pragma unroll
    for (int i = 0; i < 8; i++) {
        int row = base + eb + 2 * i;
        if (row < NN) {
            float* o = O + (size_t)row * DD + j0;
#pragma unroll
            for (int c = 0; c < 4; c++) *(float2*)(o + 2 * c) = unpack2(acc[i][c]);
        }
    }
}

// ---------------- K2: fused edge update + scatter-add ----------------
__global__ void __launch_bounds__(256, 1)
edge_kernel(const float* __restrict__ edge,
            const int* __restrict__ src_idx, const int* __restrict__ tgt_idx,
            const float* __restrict__ ln_g, const float* __restrict__ ln_b,
            float* __restrict__ edge_out) {
    extern __shared__ float sm[];
    float* ws  = sm;                    // 16384 floats
    float* xs  = ws + DD * DD;          // 128*132 = 16896 floats (edge tile, kept for residual)
    float* msg = xs + 128 * 132;        // 16896 floats
    const int tid = threadIdx.x;
    const int base = blockIdx.x * 128;
    load_w(ws, g_WtE, DD * DD, tid, 256);
    load_x<128, 132>(xs, edge, base, NE, tid, 256);
    __syncthreads();

    u64 acc[8][4];
    gemm_tile<8, 128, 132>(xs, ws, tid, acc);

    const int lane = tid & 31;
    const int w = tid >> 5;
    const int j0 = (lane & 15) << 3;
    const int eb = w * 16 + (lane >> 4);
#pragma unroll
    for (int i = 0; i < 8; i++) {
        float* m = msg + (eb + 2 * i) * 132 + j0;
#pragma unroll
        for (int c = 0; c < 4; c++) *(float2*)(m + 2 * c) = unpack2(acc[i][c]);
    }
    __syncwarp();

    // epilogue: warp w handles its own 16 edge rows [16w, 16w+16)
    const int nE = (NE - base < 128) ? (NE - base) : 128;
    const float4 g4 = __ldg((const float4*)ln_g + lane);
    const float4 b4 = __ldg((const float4*)ln_b + lane);
    int eBeg = w * 16;
    int eEnd = w * 16 + 16; if (eEnd > nE) eEnd = nE;
    int tNext = 0; float4 gsN, gtN;
    if (eBeg < eEnd) {
        int ge = base + eBeg;
        int s = __ldg(src_idx + ge); tNext = __ldg(tgt_idx + ge);
        gsN = __ldg((const float4*)(g_srcP + (size_t)s * DD) + lane);
        gtN = __ldg((const float4*)(g_tgtP + (size_t)tNext * DD) + lane);
    }
    for (int e = eBeg; e < eEnd; e++) {
        const int tThis = tNext;
        const float4 gs = gsN, gt = gtN;
        if (e + 1 < eEnd) {   // depth-1 prefetch of next edge's gathers
            int ge1 = base + e + 1;
            int s1 = __ldg(src_idx + ge1); tNext = __ldg(tgt_idx + ge1);
            gsN = __ldg((const float4*)(g_srcP + (size_t)s1 * DD) + lane);
            gtN = __ldg((const float4*)(g_tgtP + (size_t)tNext * DD) + lane);
        }
        const float4 mg = *(const float4*)(msg + e * 132 + 4 * lane);
        float u0 = silu(mg.x + gs.x + gt.x);
        float u1 = silu(mg.y + gs.y + gt.y);
        float u2 = silu(mg.z + gs.z + gt.z);
        float u3 = silu(mg.w + gs.w + gt.w);
        float s1r = (u0 + u1) + (u2 + u3);
        float s2r = fmaf(u0, u0, fmaf(u1, u1, fmaf(u2, u2, u3 * u3)));
#pragma unroll
        for (int o = 16; o > 0; o >>= 1) {
            s1r += __shfl_xor_sync(0xffffffffu, s1r, o);
            s2r += __shfl_xor_sync(0xffffffffu, s2r, o);
        }
        const float mean = s1r * (1.0f / 128.0f);
        const float var  = s2r * (1.0f / 128.0f) - mean * mean;
        const float rstd = rsqrtf(var + 1e-5f);
        const float4 res = *(const float4*)(xs + e * 132 + 4 * lane);
        float4 o4;
        o4.x = res.x + (u0 - mean) * rstd * g4.x + b4.x;
        o4.y = res.y + (u1 - mean) * rstd * g4.y + b4.y;
        o4.z = res.z + (u2 - mean) * rstd * g4.z + b4.z;
        o4.w = res.w + (u3 - mean) * rstd * g4.w + b4.w;
        const int ge = base + e;
        *(float4*)(edge_out + (size_t)ge * DD + 4 * lane) = o4;
        float* ap = g_agg + (size_t)tThis * DD + 4 * lane;
        asm volatile("red.global.add.v4.f32 [%0], {%1,%2,%3,%4};"
                     :: "l"(ap), "f"(o4.x), "f"(o4.y), "f"(o4.z), "f"(o4.w) : "memory");
    }
}

// ---------------- K3: fused target-node update (K=256 GEMM + silu + LN + residual) ----------------
__global__ void __launch_bounds__(256, 1)
node_out_kernel(const float* __restrict__ tgt,
                const float* __restrict__ ln_g, const float* __restrict__ ln_b,
                float* __restrict__ tgt_out) {
    extern __shared__ float sm[];
    float* ws = sm;                 // 2*128*128 = 32768 floats (128 KB)
    float* xs = ws + 2 * DD * DD;   // 64 rows x pitch 260: [agg | tgt]
    const int tid = threadIdx.x;
    const int base = blockIdx.x * 64;
    load_w(ws, g_WtN, 2 * DD * DD, tid, 256);
    for (int i = tid; i < 64 * 64; i += 256) {
        int r = i >> 6, c = i & 63;
        float4 v = make_float4(0.f, 0.f, 0.f, 0.f);
        int row = base + r;
        if (row < NN) {
            if (c < 32) v = __ldg((const float4*)(g_agg + (size_t)row * DD) + c);
            else        v = __ldg((const float4*)(tgt  + (size_t)row * DD) + (c - 32));
        }
        *(float4*)(xs + r * 260 + 4 * c) = v;
    }
    __syncthreads();

    u64 acc[4][4];
    gemm_tile<4, 256, 260>(xs, ws, tid, acc);

    const int lane = tid & 31;
    const int w = tid >> 5;
    const int j0 = (lane & 15) << 3;
    const int eb = w * 8 + (lane >> 4);
    // overwrite the agg-half of own rows with msg (per-warp private rows)
#pragma unroll
    for (int i = 0; i < 4; i++) {
        float* m = xs + (eb + 2 * i) * 260 + j0;
#pragma unroll
        for (int c = 0; c < 4; c++) *(float2*)(m + 2 * c) = unpack2(acc[i][c]);
    }
    __syncwarp();

    const int nR = (NN - base < 64) ? (NN - base) : 64;
    const float4 g4 = __ldg((const float4*)ln_g + lane);
    const float4 b4 = __ldg((const float4*)ln_b + lane);
    for (int t = 0; t < 8; t++) {
        int r = w * 8 + t;
        if (r >= nR) break;
        const float4 mg = *(const float4*)(xs + r * 260 + 4 * lane);
        float u0 = silu(mg.x), u1 = silu(mg.y), u2 = silu(mg.z), u3 = silu(mg.w);
        float s1r = (u0 + u1) + (u2 + u3);
        float s2r = fmaf(u0, u0, fmaf(u1, u1, fmaf(u2, u2, u3 * u3)));
#pragma unroll
        for (int o = 16; o > 0; o >>= 1) {
            s1r += __shfl_xor_sync(0xffffffffu, s1r, o);
            s2r += __shfl_xor_sync(0xffffffffu, s2r, o);
        }
        const float mean = s1r * (1.0f / 128.0f);
        const float var  = s2r * (1.0f / 128.0f) - mean * mean;
        const float rstd = rsqrtf(var + 1e-5f);
        const float4 res = *(const float4*)(xs + r * 260 + 128 + 4 * lane);
        float4 o4;
        o4.x = res.x + (u0 - mean) * rstd * g4.x + b4.x;
        o4.y = res.y + (u1 - mean) * rstd * g4.y + b4.y;
        o4.z = res.z + (u2 - mean) * rstd * g4.z + b4.z;
        o4.w = res.w + (u3 - mean) * rstd * g4.w + b4.w;
        *(float4*)(tgt_out + (size_t)(base + r) * DD + 4 * lane) = o4;
    }
}

// ---------------- launcher ----------------
extern "C" void kernel_launch(void* const* d_in, const int* in_sizes, int n_in,
                              void* d_out, int out_size) {
    (void)in_sizes; (void)n_in; (void)out_size;
    const float* src     = (const float*)d_in[0];
    const float* tgt     = (const float*)d_in[1];
    const float* edge    = (const float*)d_in[2];
    const int*   src_idx = (const int*)d_in[3];
    const int*   tgt_idx = (const int*)d_in[4];
    const float* W_s2e   = (const float*)d_in[5];
    const float* W_t2e   = (const float*)d_in[6];
    const float* W_e2e   = (const float*)d_in[7];
    const float* W_e2t   = (const float*)d_in[8];
    const float* W_t2t   = (const float*)d_in[9];
    const float* ln1_g   = (const float*)d_in[10];
    const float* ln1_b   = (const float*)d_in[11];
    const float* ln2_g   = (const float*)d_in[12];
    const float* ln2_b   = (const float*)d_in[13];

    float* edge_out = (float*)d_out;
    float* tgt_out  = (float*)d_out + (size_t)NE * DD;

    const int SMEM1 = (DD * DD + 128 * 132) * 4;               // 133120 B
    const int SMEM2 = (DD * DD + 2 * 128 * 132) * 4;           // 200704 B
    const int SMEM3 = (2 * DD * DD + 64 * 260) * 4;            // 197632 B
    cudaFuncSetAttribute(node_proj_kernel, cudaFuncAttributeMaxDynamicSharedMemorySize, SMEM1);
    cudaFuncSetAttribute(edge_kernel,      cudaFuncAttributeMaxDynamicSharedMemorySize, SMEM2);
    cudaFuncSetAttribute(node_out_kernel,  cudaFuncAttributeMaxDynamicSharedMemorySize, SMEM3);

    prep_kernel<<<(DD * DD + 255) / 256, 256>>>(W_s2e, W_t2e, W_e2e, W_e2t, W_t2t);
    zero_agg_kernel<<<1024, 256>>>();
    node_proj_kernel<<<dim3((NN + 127) / 128, 2), 256, SMEM1>>>(src, tgt);
    edge_kernel<<<(NE + 127) / 128, 256, SMEM2>>>(edge, src_idx, tgt_idx, ln1_g, ln1_b, edge_out);
    node_out_kernel<<<(NN + 63) / 64, 256, SMEM3>>>(tgt, ln2_g, ln2_b, tgt_out);
}

// round 4
// speedup vs baseline: 1.3244x; 1.3244x over previous
#include <cuda_runtime.h>

#define NN 50000
#define NE 500000
#define DD 128
#define TILE 64
#define PITCH 132
#define NTHR 256

// ---------------- device scratch ----------------
__device__ float g_srcP[(size_t)NN * DD];   // src @ W_s2e^T
__device__ float g_tgtP[(size_t)NN * DD];   // tgt @ W_t2e^T
__device__ float g_aggP[(size_t)NN * DD];   // agg @ W_e2t^T
__device__ float g_agg [(size_t)NN * DD];   // segment_sum(edge_out)
__device__ float g_WtS[DD * DD];
__device__ float g_WtT[DD * DD];
__device__ float g_WtE[DD * DD];
__device__ float g_WtU[DD * DD];            // W_e2t^T
__device__ float g_WtV[DD * DD];            // W_t2t^T

typedef unsigned long long u64;

__device__ __forceinline__ u64 pack2(float lo, float hi) {
    u64 r; asm("mov.b64 %0,{%1,%2};" : "=l"(r) : "f"(lo), "f"(hi)); return r;
}
__device__ __forceinline__ float2 unpack2(u64 v) {
    float2 f; asm("mov.b64 {%0,%1},%2;" : "=f"(f.x), "=f"(f.y) : "l"(v)); return f;
}
__device__ __forceinline__ u64 ffma2(u64 a, u64 b, u64 c) {
    u64 d; asm("fma.rn.f32x2 %0,%1,%2,%3;" : "=l"(d) : "l"(a), "l"(b), "l"(c)); return d;
}
__device__ __forceinline__ float silu(float x) { return x * (1.0f / (1.0f + __expf(-x))); }

// ---------------- K0: transpose weights ----------------
__global__ void prep_kernel(const float* __restrict__ Ws2e, const float* __restrict__ Wt2e,
                            const float* __restrict__ We2e, const float* __restrict__ We2t,
                            const float* __restrict__ Wt2t) {
    int i = blockIdx.x * blockDim.x + threadIdx.x;
    if (i < DD * DD) {
        int k = i >> 7, j = i & 127;
        int s = j * DD + k;
        g_WtS[i] = Ws2e[s];
        g_WtT[i] = Wt2e[s];
        g_WtE[i] = We2e[s];
        g_WtU[i] = We2t[s];
        g_WtV[i] = Wt2t[s];
    }
}

// ---------------- Kz: zero aggregation buffer ----------------
__global__ void zero_agg_kernel() {
    const size_t n = (size_t)NN * DD / 4;
    float4 z = make_float4(0.f, 0.f, 0.f, 0.f);
    for (size_t i = blockIdx.x * (size_t)blockDim.x + threadIdx.x; i < n;
         i += (size_t)gridDim.x * blockDim.x)
        ((float4*)g_agg)[i] = z;
}

// ---------------- helpers ----------------
__device__ __forceinline__ void load_w(float* ws, const float* __restrict__ gw, int tid) {
    const float4* s = (const float4*)gw;
    float4* d = (float4*)ws;
#pragma unroll
    for (int it = 0; it < (DD * DD / 4) / NTHR; it++) d[tid + it * NTHR] = s[tid + it * NTHR];
}

__device__ __forceinline__ void load_x64(float* xs, const float* __restrict__ g,
                                         int base, int M, int tid) {
#pragma unroll
    for (int it = 0; it < (TILE * 32) / NTHR; it++) {
        int i = tid + it * NTHR;
        int r = i >> 5, c = i & 31;
        float4 v = make_float4(0.f, 0.f, 0.f, 0.f);
        int row = base + r;
        if (row < M) v = __ldg((const float4*)(g + (size_t)row * DD) + c);
        *(float4*)(xs + r * PITCH + 4 * c) = v;
    }
}

// GEMM micro: 64 rows x 128 cols, K=128. Warp w owns rows [8w, 8w+8).
// lane: j0=(lane&15)*8 cols, row parity = lane>>4. Each thread: 4 rows x 8 cols.
// Weights loaded as ulonglong2 (already-packed f32x2 pairs -> zero pack movs).
__device__ __forceinline__ void gemm64(const float* __restrict__ xs,
                                       const float* __restrict__ ws,
                                       int tid, u64 (&acc)[4][4]) {
    const int lane = tid & 31;
    const int j0 = (lane & 15) << 3;
    const int eb = ((tid >> 5) << 3) + (lane >> 4);
#pragma unroll
    for (int i = 0; i < 4; i++)
#pragma unroll
        for (int c = 0; c < 4; c++) acc[i][c] = 0ull;
    const float* xp = xs + eb * PITCH;
#pragma unroll 4
    for (int k = 0; k < DD; k += 2) {
        ulonglong2 w00 = *(const ulonglong2*)(ws + k * DD + j0);
        ulonglong2 w01 = *(const ulonglong2*)(ws + k * DD + j0 + 4);
        ulonglong2 w10 = *(const ulonglong2*)(ws + (k + 1) * DD + j0);
        ulonglong2 w11 = *(const ulonglong2*)(ws + (k + 1) * DD + j0 + 4);
#pragma unroll
        for (int i = 0; i < 4; i++) {
            float2 xv = *(const float2*)(xp + i * 2 * PITCH + k);
            u64 xa = pack2(xv.x, xv.x);
            u64 xb = pack2(xv.y, xv.y);
            acc[i][0] = ffma2(xa, w00.x, acc[i][0]);
            acc[i][1] = ffma2(xa, w00.y, acc[i][1]);
            acc[i][2] = ffma2(xa, w01.x, acc[i][2]);
            acc[i][3] = ffma2(xa, w01.y, acc[i][3]);
            acc[i][0] = ffma2(xb, w10.x, acc[i][0]);
            acc[i][1] = ffma2(xb, w10.y, acc[i][1]);
            acc[i][2] = ffma2(xb, w11.x, acc[i][2]);
            acc[i][3] = ffma2(xb, w11.y, acc[i][3]);
        }
    }
}

// ---------------- K1: persistent projection O = X @ W^T ----------------
__global__ void __launch_bounds__(NTHR, 2)
proj_kernel(const float* __restrict__ Xin, int mode) {
    extern __shared__ float sm[];
    float* ws = sm;
    float* xs = sm + DD * DD;
    const int tid = threadIdx.x;
    const float* X; const float* W; float* O;
    if (mode == 0)      { X = Xin;   W = g_WtS; O = g_srcP; }
    else if (mode == 1) { X = Xin;   W = g_WtT; O = g_tgtP; }
    else                { X = g_agg; W = g_WtU; O = g_aggP; }
    load_w(ws, W, tid);
    const int lane = tid & 31;
    const int j0 = (lane & 15) << 3;
    const int eb = ((tid >> 5) << 3) + (lane >> 4);
    const int NT = (NN + TILE - 1) / TILE;
    for (int t = blockIdx.x; t < NT; t += gridDim.x) {
        const int base = t * TILE;
        __syncthreads();
        load_x64(xs, X, base, NN, tid);
        __syncthreads();
        u64 acc[4][4];
        gemm64(xs, ws, tid, acc);
#pragma unroll
        for (int i = 0; i < 4; i++) {
            int row = base + eb + 2 * i;
            if (row < NN) {
                float2 m0 = unpack2(acc[i][0]), m1 = unpack2(acc[i][1]);
                float2 m2 = unpack2(acc[i][2]), m3 = unpack2(acc[i][3]);
                float* o = O + (size_t)row * DD + j0;
                *(float4*)o       = make_float4(m0.x, m0.y, m1.x, m1.y);
                *(float4*)(o + 4) = make_float4(m2.x, m2.y, m3.x, m3.y);
            }
        }
    }
}

// ---------------- K2: persistent fused edge update + scatter-add ----------------
__global__ void __launch_bounds__(NTHR, 2)
edge_kernel(const float* __restrict__ edge,
            const int* __restrict__ src_idx, const int* __restrict__ tgt_idx,
            const float* __restrict__ ln_g, const float* __restrict__ ln_b,
            float* __restrict__ edge_out) {
    extern __shared__ float sm[];
    float* ws  = sm;
    float* xs  = sm + DD * DD;
    float* lnp = xs + TILE * PITCH;
    const int tid = threadIdx.x;
    load_w(ws, g_WtE, tid);
    for (int i = tid; i < DD; i += NTHR) { lnp[i] = ln_g[i]; lnp[DD + i] = ln_b[i]; }
    const int lane = tid & 31;
    const int j0 = (lane & 15) << 3;
    const int eb = ((tid >> 5) << 3) + (lane >> 4);
    const int NT = (NE + TILE - 1) / TILE;

    for (int t = blockIdx.x; t < NT; t += gridDim.x) {
        const int base = t * TILE;
        __syncthreads();
        load_x64(xs, edge, base, NE, tid);
        __syncthreads();
        u64 acc[4][4];
        gemm64(xs, ws, tid, acc);

        const int nE = (NE - base < TILE) ? (NE - base) : TILE;
        int sidx[4], tidx[4];
#pragma unroll
        for (int i = 0; i < 4; i++) {
            int r = eb + 2 * i;
            int ge = base + (r < nE ? r : 0);
            sidx[i] = __ldg(src_idx + ge);
            tidx[i] = __ldg(tgt_idx + ge);
        }
        const float4 lg0 = *(const float4*)(lnp + j0);
        const float4 lg1 = *(const float4*)(lnp + j0 + 4);
        const float4 lb0 = *(const float4*)(lnp + DD + j0);
        const float4 lb1 = *(const float4*)(lnp + DD + j0 + 4);

        // batched gathers, depth-1 prefetch
        float4 ns0 = __ldg((const float4*)(g_srcP + (size_t)sidx[0] * DD + j0));
        float4 ns1 = __ldg((const float4*)(g_srcP + (size_t)sidx[0] * DD + j0) + 1);
        float4 nt0 = __ldg((const float4*)(g_tgtP + (size_t)tidx[0] * DD + j0));
        float4 nt1 = __ldg((const float4*)(g_tgtP + (size_t)tidx[0] * DD + j0) + 1);
#pragma unroll
        for (int i = 0; i < 4; i++) {
            const float4 cs0 = ns0, cs1 = ns1, ct0 = nt0, ct1 = nt1;
            if (i < 3) {
                ns0 = __ldg((const float4*)(g_srcP + (size_t)sidx[i + 1] * DD + j0));
                ns1 = __ldg((const float4*)(g_srcP + (size_t)sidx[i + 1] * DD + j0) + 1);
                nt0 = __ldg((const float4*)(g_tgtP + (size_t)tidx[i + 1] * DD + j0));
                nt1 = __ldg((const float4*)(g_tgtP + (size_t)tidx[i + 1] * DD + j0) + 1);
            }
            float2 m0 = unpack2(acc[i][0]), m1 = unpack2(acc[i][1]);
            float2 m2 = unpack2(acc[i][2]), m3 = unpack2(acc[i][3]);
            float u0 = silu(m0.x + cs0.x + ct0.x);
            float u1 = silu(m0.y + cs0.y + ct0.y);
            float u2 = silu(m1.x + cs0.z + ct0.z);
            float u3 = silu(m1.y + cs0.w + ct0.w);
            float u4 = silu(m2.x + cs1.x + ct1.x);
            float u5 = silu(m2.y + cs1.y + ct1.y);
            float u6 = silu(m3.x + cs1.z + ct1.z);
            float u7 = silu(m3.y + cs1.w + ct1.w);
            float s1 = ((u0 + u1) + (u2 + u3)) + ((u4 + u5) + (u6 + u7));
            float s2 = fmaf(u0, u0, fmaf(u1, u1, fmaf(u2, u2, fmaf(u3, u3,
                       fmaf(u4, u4, fmaf(u5, u5, fmaf(u6, u6, u7 * u7)))))));
#pragma unroll
            for (int o = 8; o > 0; o >>= 1) {
                s1 += __shfl_xor_sync(0xffffffffu, s1, o);
                s2 += __shfl_xor_sync(0xffffffffu, s2, o);
            }
            const float mean = s1 * (1.0f / 128.0f);
            const float var  = s2 * (1.0f / 128.0f) - mean * mean;
            const float rstd = rsqrtf(var + 1e-5f);
            const int r = eb + 2 * i;
            const float* xr = xs + r * PITCH + j0;
            const float4 r0 = *(const float4*)xr;
            const float4 r1 = *(const float4*)(xr + 4);
            float4 o0, o1;
            o0.x = r0.x + (u0 - mean) * rstd * lg0.x + lb0.x;
            o0.y = r0.y + (u1 - mean) * rstd * lg0.y + lb0.y;
            o0.z = r0.z + (u2 - mean) * rstd * lg0.z + lb0.z;
            o0.w = r0.w + (u3 - mean) * rstd * lg0.w + lb0.w;
            o1.x = r1.x + (u4 - mean) * rstd * lg1.x + lb1.x;
            o1.y = r1.y + (u5 - mean) * rstd * lg1.y + lb1.y;
            o1.z = r1.z + (u6 - mean) * rstd * lg1.z + lb1.z;
            o1.w = r1.w + (u7 - mean) * rstd * lg1.w + lb1.w;
            if (r < nE) {
                const int ge = base + r;
                *(float4*)(edge_out + (size_t)ge * DD + j0)     = o0;
                *(float4*)(edge_out + (size_t)ge * DD + j0 + 4) = o1;
                float* ap = g_agg + (size_t)tidx[i] * DD + j0;
                asm volatile("red.global.add.v4.f32 [%0], {%1,%2,%3,%4};"
                             :: "l"(ap), "f"(o0.x), "f"(o0.y), "f"(o0.z), "f"(o0.w) : "memory");
                asm volatile("red.global.add.v4.f32 [%0], {%1,%2,%3,%4};"
                             :: "l"(ap + 4), "f"(o1.x), "f"(o1.y), "f"(o1.z), "f"(o1.w) : "memory");
            }
        }
    }
}

// ---------------- K3: persistent fused node update ----------------
// msg = tgt @ W_t2t^T + g_aggP;  tgt_out = tgt + LN(silu(msg))
__global__ void __launch_bounds__(NTHR, 2)
node_out_kernel(const float* __restrict__ tgt,
                const float* __restrict__ ln_g, const float* __restrict__ ln_b,
                float* __restrict__ tgt_out) {
    extern __shared__ float sm[];
    float* ws  = sm;
    float* xs  = sm + DD * DD;
    float* lnp = xs + TILE * PITCH;
    const int tid = threadIdx.x;
    load_w(ws, g_WtV, tid);
    for (int i = tid; i < DD; i += NTHR) { lnp[i] = ln_g[i]; lnp[DD + i] = ln_b[i]; }
    const int lane = tid & 31;
    const int j0 = (lane & 15) << 3;
    const int eb = ((tid >> 5) << 3) + (lane >> 4);
    const int NT = (NN + TILE - 1) / TILE;

    for (int t = blockIdx.x; t < NT; t += gridDim.x) {
        const int base = t * TILE;
        __syncthreads();
        load_x64(xs, tgt, base, NN, tid);
        __syncthreads();
        u64 acc[4][4];
        gemm64(xs, ws, tid, acc);

        const int nR = (NN - base < TILE) ? (NN - base) : TILE;
        const float4 lg0 = *(const float4*)(lnp + j0);
        const float4 lg1 = *(const float4*)(lnp + j0 + 4);
        const float4 lb0 = *(const float4*)(lnp + DD + j0);
        const float4 lb1 = *(const float4*)(lnp + DD + j0 + 4);
#pragma unroll
        for (int i = 0; i < 4; i++) {
            const int r = eb + 2 * i;
            const int row = base + (r < nR ? r : 0);
            const float4 a0 = __ldg((const float4*)(g_aggP + (size_t)row * DD + j0));
            const float4 a1 = __ldg((const float4*)(g_aggP + (size_t)row * DD + j0) + 1);
            float2 m0 = unpack2(acc[i][0]), m1 = unpack2(acc[i][1]);
            float2 m2 = unpack2(acc[i][2]), m3 = unpack2(acc[i][3]);
            float u0 = silu(m0.x + a0.x);
            float u1 = silu(m0.y + a0.y);
            float u2 = silu(m1.x + a0.z);
            float u3 = silu(m1.y + a0.w);
            float u4 = silu(m2.x + a1.x);
            float u5 = silu(m2.y + a1.y);
            float u6 = silu(m3.x + a1.z);
            float u7 = silu(m3.y + a1.w);
            float s1 = ((u0 + u1) + (u2 + u3)) + ((u4 + u5) + (u6 + u7));
            float s2 = fmaf(u0, u0, fmaf(u1, u1, fmaf(u2, u2, fmaf(u3, u3,
                       fmaf(u4, u4, fmaf(u5, u5, fmaf(u6, u6, u7 * u7)))))));
#pragma unroll
            for (int o = 8; o > 0; o >>= 1) {
                s1 += __shfl_xor_sync(0xffffffffu, s1, o);
                s2 += __shfl_xor_sync(0xffffffffu, s2, o);
            }
            const float mean = s1 * (1.0f / 128.0f);
            const float var  = s2 * (1.0f / 128.0f) - mean * mean;
            const float rstd = rsqrtf(var + 1e-5f);
            const float* xr = xs + r * PITCH + j0;
            const float4 r0 = *(const float4*)xr;
            const float4 r1 = *(const float4*)(xr + 4);
            float4 o0, o1;
            o0.x = r0.x + (u0 - mean) * rstd * lg0.x + lb0.x;
            o0.y = r0.y + (u1 - mean) * rstd * lg0.y + lb0.y;
            o0.z = r0.z + (u2 - mean) * rstd * lg0.z + lb0.z;
            o0.w = r0.w + (u3 - mean) * rstd * lg0.w + lb0.w;
            o1.x = r1.x + (u4 - mean) * rstd * lg1.x + lb1.x;
            o1.y = r1.y + (u5 - mean) * rstd * lg1.y + lb1.y;
            o1.z = r1.z + (u6 - mean) * rstd * lg1.z + lb1.z;
            o1.w = r1.w + (u7 - mean) * rstd * lg1.w + lb1.w;
            if (r < nR) {
                *(float4*)(tgt_out + (size_t)(base + r) * DD + j0)     = o0;
                *(float4*)(tgt_out + (size_t)(base + r) * DD + j0 + 4) = o1;
            }
        }
    }
}

// ---------------- launcher ----------------
extern "C" void kernel_launch(void* const* d_in, const int* in_sizes, int n_in,
                              void* d_out, int out_size) {
    (void)in_sizes; (void)n_in; (void)out_size;
    const float* src     = (const float*)d_in[0];
    const float* tgt     = (const float*)d_in[1];
    const float* edge    = (const float*)d_in[2];
    const int*   src_idx = (const int*)d_in[3];
    const int*   tgt_idx = (const int*)d_in[4];
    const float* W_s2e   = (const float*)d_in[5];
    const float* W_t2e   = (const float*)d_in[6];
    const float* W_e2e   = (const float*)d_in[7];
    const float* W_e2t   = (const float*)d_in[8];
    const float* W_t2t   = (const float*)d_in[9];
    const float* ln1_g   = (const float*)d_in[10];
    const float* ln1_b   = (const float*)d_in[11];
    const float* ln2_g   = (const float*)d_in[12];
    const float* ln2_b   = (const float*)d_in[13];

    float* edge_out = (float*)d_out;
    float* tgt_out  = (float*)d_out + (size_t)NE * DD;

    const int SMEMP = (DD * DD + TILE * PITCH) * 4;            // 99,328 B
    const int SMEMF = (DD * DD + TILE * PITCH + 2 * DD) * 4;   // 100,352 B
    cudaFuncSetAttribute(proj_kernel,     cudaFuncAttributeMaxDynamicSharedMemorySize, SMEMP);
    cudaFuncSetAttribute(edge_kernel,     cudaFuncAttributeMaxDynamicSharedMemorySize, SMEMF);
    cudaFuncSetAttribute(node_out_kernel, cudaFuncAttributeMaxDynamicSharedMemorySize, SMEMF);

    const int GP = 296;  // 2 CTAs/SM x 148 SMs, persistent

    prep_kernel<<<(DD * DD + 255) / 256, 256>>>(W_s2e, W_t2e, W_e2e, W_e2t, W_t2t);
    zero_agg_kernel<<<1024, 256>>>();
    proj_kernel<<<GP, NTHR, SMEMP>>>(src, 0);
    proj_kernel<<<GP, NTHR, SMEMP>>>(tgt, 1);
    edge_kernel<<<GP, NTHR, SMEMF>>>(edge, src_idx, tgt_idx, ln1_g, ln1_b, edge_out);
    proj_kernel<<<GP, NTHR, SMEMP>>>(nullptr, 2);
    node_out_kernel<<<GP, NTHR, SMEMF>>>(tgt, ln2_g, ln2_b, tgt_out);
}

// round 7
// speedup vs baseline: 1.3608x; 1.0275x over previous
#include <cuda_runtime.h>
#include <cuda_bf16.h>

#define NN 50000
#define NE 500000
#define DD 128
#define TILE 64
#define PITCH 132
#define NTHR 256

// ---- edge HMMA kernel config ----
#define ET 128
#define NT_E ((NE + ET - 1) / ET)       // 3907

// smem byte offsets (edge kernel); all tiles: 128 rows x 128 bf16, pitch 256B, 16B-chunk XOR swizzle
#define SM_BHI 0
#define SM_BLO 32768
#define SM_AHI 65536
#define SM_ALO 98304
#define SM_LN  131072                   // 1024 B: g[128] | b[128]
#define SM_SUMS 132096                  // 128 rows x 2 halves x float2 = 2048 B
#define SM_EDGE_TOTAL 134144

// ---------------- device scratch ----------------
__device__ float g_srcP[(size_t)NN * DD];
__device__ float g_tgtP[(size_t)NN * DD];
__device__ float g_aggP[(size_t)NN * DD];
__device__ float g_agg [(size_t)NN * DD];
__device__ float g_WtS[DD * DD];
__device__ float g_WtT[DD * DD];
__device__ float g_WtU[DD * DD];
__device__ float g_WtV[DD * DD];

typedef unsigned long long u64;

__device__ __forceinline__ u64 pack2(float lo, float hi) {
    u64 r; asm("mov.b64 %0,{%1,%2};" : "=l"(r) : "f"(lo), "f"(hi)); return r;
}
__device__ __forceinline__ float2 unpack2(u64 v) {
    float2 f; asm("mov.b64 {%0,%1},%2;" : "=f"(f.x), "=f"(f.y) : "l"(v)); return f;
}
__device__ __forceinline__ u64 ffma2(u64 a, u64 b, u64 c) {
    u64 d; asm("fma.rn.f32x2 %0,%1,%2,%3;" : "=l"(d) : "l"(a), "l"(b), "l"(c)); return d;
}
__device__ __forceinline__ float silu(float x) { return x * (1.0f / (1.0f + __expf(-x))); }

// ---------------- warp-mma helpers ----------------
__device__ __forceinline__ unsigned smem_u32(const void* p) {
    unsigned a;
    asm("{ .reg .u64 t; cvta.to.shared.u64 t, %1; cvt.u32.u64 %0, t; }" : "=r"(a) : "l"(p));
    return a;
}
__device__ __forceinline__ void ldsm4(unsigned r[4], unsigned addr) {
    asm volatile("ldmatrix.sync.aligned.m8n8.x4.shared.b16 {%0,%1,%2,%3}, [%4];"
                 : "=r"(r[0]), "=r"(r[1]), "=r"(r[2]), "=r"(r[3]) : "r"(addr));
}
__device__ __forceinline__ void mma16816(float c[4], const unsigned a[4],
                                         unsigned b0, unsigned b1) {
    asm volatile("mma.sync.aligned.m16n8k16.row.col.f32.bf16.bf16.f32 "
                 "{%0,%1,%2,%3}, {%4,%5,%6,%7}, {%8,%9}, {%0,%1,%2,%3};"
                 : "+f"(c[0]), "+f"(c[1]), "+f"(c[2]), "+f"(c[3])
                 : "r"(a[0]), "r"(a[1]), "r"(a[2]), "r"(a[3]), "r"(b0), "r"(b1));
}
__device__ __forceinline__ unsigned pack_bf2(__nv_bfloat16 a, __nv_bfloat16 b) {
    __nv_bfloat162 t = __halves2bfloat162(a, b);
    return *reinterpret_cast<unsigned*>(&t);
}

// store 4 fp32 as bf16 hi/lo into swizzled tile: row pitch 256B, 16B chunk XOR (row&7)
__device__ __forceinline__ void store_hilo(char* smem, int offH, int offL,
                                           int row, int c0, float4 v) {
    unsigned chunk = ((unsigned)c0 >> 3) ^ ((unsigned)row & 7u);
    unsigned off = (unsigned)row * 256u + chunk * 16u + ((unsigned)c0 & 7u) * 2u;
    __nv_bfloat16 hx = __float2bfloat16(v.x);
    __nv_bfloat16 hy = __float2bfloat16(v.y);
    __nv_bfloat16 hz = __float2bfloat16(v.z);
    __nv_bfloat16 hw = __float2bfloat16(v.w);
    __nv_bfloat16 lx = __float2bfloat16(v.x - __bfloat162float(hx));
    __nv_bfloat16 ly = __float2bfloat16(v.y - __bfloat162float(hy));
    __nv_bfloat16 lz = __float2bfloat16(v.z - __bfloat162float(hz));
    __nv_bfloat16 lw = __float2bfloat16(v.w - __bfloat162float(hw));
    *(uint2*)(smem + offH + off) = make_uint2(pack_bf2(hx, hy), pack_bf2(hz, hw));
    *(uint2*)(smem + offL + off) = make_uint2(pack_bf2(lx, ly), pack_bf2(lz, lw));
}

// ---------------- K0: transpose weights (FFMA kernels) ----------------
__global__ void prep_kernel(const float* __restrict__ Ws2e, const float* __restrict__ Wt2e,
                            const float* __restrict__ We2t, const float* __restrict__ Wt2t) {
    int i = blockIdx.x * blockDim.x + threadIdx.x;
    if (i < DD * DD) {
        int k = i >> 7, j = i & 127;
        int s = j * DD + k;
        g_WtS[i] = Ws2e[s];
        g_WtT[i] = Wt2e[s];
        g_WtU[i] = We2t[s];
        g_WtV[i] = Wt2t[s];
    }
}

// ---------------- Kz: zero aggregation buffer ----------------
__global__ void zero_agg_kernel() {
    const size_t n = (size_t)NN * DD / 4;
    float4 z = make_float4(0.f, 0.f, 0.f, 0.f);
    for (size_t i = blockIdx.x * (size_t)blockDim.x + threadIdx.x; i < n;
         i += (size_t)gridDim.x * blockDim.x)
        ((float4*)g_agg)[i] = z;
}

// ---------------- FFMA GEMM helpers (proj / node kernels) ----------------
__device__ __forceinline__ void load_w(float* ws, const float* __restrict__ gw, int tid) {
    const float4* s = (const float4*)gw;
    float4* d = (float4*)ws;
#pragma unroll
    for (int it = 0; it < (DD * DD / 4) / NTHR; it++) d[tid + it * NTHR] = s[tid + it * NTHR];
}

__device__ __forceinline__ void load_x64(float* xs, const float* __restrict__ g,
                                         int base, int M, int tid) {
#pragma unroll
    for (int it = 0; it < (TILE * 32) / NTHR; it++) {
        int i = tid + it * NTHR;
        int r = i >> 5, c = i & 31;
        float4 v = make_float4(0.f, 0.f, 0.f, 0.f);
        int row = base + r;
        if (row < M) v = __ldg((const float4*)(g + (size_t)row * DD) + c);
        *(float4*)(xs + r * PITCH + 4 * c) = v;
    }
}

__device__ __forceinline__ void gemm64(const float* __restrict__ xs,
                                       const float* __restrict__ ws,
                                       int tid, u64 (&acc)[4][4]) {
    const int lane = tid & 31;
    const int j0 = (lane & 15) << 3;
    const int eb = ((tid >> 5) << 3) + (lane >> 4);
#pragma unroll
    for (int i = 0; i < 4; i++)
#pragma unroll
        for (int c = 0; c < 4; c++) acc[i][c] = 0ull;
    const float* xp = xs + eb * PITCH;
#pragma unroll 4
    for (int k = 0; k < DD; k += 2) {
        ulonglong2 w00 = *(const ulonglong2*)(ws + k * DD + j0);
        ulonglong2 w01 = *(const ulonglong2*)(ws + k * DD + j0 + 4);
        ulonglong2 w10 = *(const ulonglong2*)(ws + (k + 1) * DD + j0);
        ulonglong2 w11 = *(const ulonglong2*)(ws + (k + 1) * DD + j0 + 4);
#pragma unroll
        for (int i = 0; i < 4; i++) {
            float2 xv = *(const float2*)(xp + i * 2 * PITCH + k);
            u64 xa = pack2(xv.x, xv.x);
            u64 xb = pack2(xv.y, xv.y);
            acc[i][0] = ffma2(xa, w00.x, acc[i][0]);
            acc[i][1] = ffma2(xa, w00.y, acc[i][1]);
            acc[i][2] = ffma2(xa, w01.x, acc[i][2]);
            acc[i][3] = ffma2(xa, w01.y, acc[i][3]);
            acc[i][0] = ffma2(xb, w10.x, acc[i][0]);
            acc[i][1] = ffma2(xb, w10.y, acc[i][1]);
            acc[i][2] = ffma2(xb, w11.x, acc[i][2]);
            acc[i][3] = ffma2(xb, w11.y, acc[i][3]);
        }
    }
}

// ---------------- K1: persistent projection O = X @ W^T ----------------
__global__ void __launch_bounds__(NTHR, 2)
proj_kernel(const float* __restrict__ Xin, int mode) {
    extern __shared__ float sm[];
    float* ws = sm;
    float* xs = sm + DD * DD;
    const int tid = threadIdx.x;
    const float* X; const float* W; float* O;
    if (mode == 0)      { X = Xin;   W = g_WtS; O = g_srcP; }
    else if (mode == 1) { X = Xin;   W = g_WtT; O = g_tgtP; }
    else                { X = g_agg; W = g_WtU; O = g_aggP; }
    load_w(ws, W, tid);
    const int lane = tid & 31;
    const int j0 = (lane & 15) << 3;
    const int eb = ((tid >> 5) << 3) + (lane >> 4);
    const int NT = (NN + TILE - 1) / TILE;
    for (int t = blockIdx.x; t < NT; t += gridDim.x) {
        const int base = t * TILE;
        __syncthreads();
        load_x64(xs, X, base, NN, tid);
        __syncthreads();
        u64 acc[4][4];
        gemm64(xs, ws, tid, acc);
#pragma unroll
        for (int i = 0; i < 4; i++) {
            int row = base + eb + 2 * i;
            if (row < NN) {
                float2 m0 = unpack2(acc[i][0]), m1 = unpack2(acc[i][1]);
                float2 m2 = unpack2(acc[i][2]), m3 = unpack2(acc[i][3]);
                float* o = O + (size_t)row * DD + j0;
                *(float4*)o       = make_float4(m0.x, m0.y, m1.x, m1.y);
                *(float4*)(o + 4) = make_float4(m2.x, m2.y, m3.x, m3.y);
            }
        }
    }
}

// ---------------- K2: HMMA (bf16x3) fused edge update + scatter-add ----------------
// D[128,128] = edge_tile @ W_e2e^T via mma.sync m16n8k16. Warp w: rows [32(w&3),+32),
// cols [64(w>>2),+64). Epilogue in registers; LN via quad shuffles + cross-warp smem sums.
__global__ void __launch_bounds__(NTHR, 1)
edge_kernel(const float* __restrict__ edge,
            const int* __restrict__ src_idx, const int* __restrict__ tgt_idx,
            const float* __restrict__ We2e,
            const float* __restrict__ ln_g, const float* __restrict__ ln_b,
            float* __restrict__ edge_out) {
    extern __shared__ __align__(128) char smem[];
    const unsigned smb = smem_u32(smem);
    const int tid = threadIdx.x;
    const int wid = tid >> 5, lane = tid & 31;

    // B = W_e2e[n][k] -> bf16 hi/lo swizzled (once per persistent CTA)
#pragma unroll
    for (int it = 0; it < 16; it++) {
        int i = tid + it * NTHR;
        int n = i >> 5, c0 = (i & 31) << 2;
        float4 v = __ldg((const float4*)(We2e + (size_t)n * DD + c0));
        store_hilo(smem, SM_BHI, SM_BLO, n, c0, v);
    }
    for (int i = tid; i < DD; i += NTHR) {
        ((float*)(smem + SM_LN))[i] = ln_g[i];
        ((float*)(smem + SM_LN))[DD + i] = ln_b[i];
    }

    const int wa = wid & 3, wb = wid >> 2;
    const int m0 = wa * 32, n0 = wb * 64;
    const int g = lane >> 2, q = lane & 3;
    const int within = lane & 7, sub = lane >> 3;

    // fixed ldmatrix lane rows
    const int rA0 = m0 + within + ((sub & 1) << 3);   // A m-tile 0
    const int rA1 = rA0 + 16;                         // A m-tile 1
    const int rBo = within + ((sub >> 1) << 3);       // B row offset within n-pair

    for (int t = blockIdx.x; t < NT_E; t += gridDim.x) {
        const int base = t * ET;
        const int nE = (NE - base < ET) ? (NE - base) : ET;

        // A tile convert (zero-padded)
#pragma unroll
        for (int it = 0; it < 16; it++) {
            int i = tid + it * NTHR;
            int r = i >> 5, c0 = (i & 31) << 2;
            float4 v = make_float4(0.f, 0.f, 0.f, 0.f);
            if (base + r < NE) v = __ldg((const float4*)(edge + (size_t)(base + r) * DD + c0));
            store_hilo(smem, SM_AHI, SM_ALO, r, c0, v);
        }
        __syncthreads();

        float acc[2][8][4];
#pragma unroll
        for (int i = 0; i < 2; i++)
#pragma unroll
            for (int j = 0; j < 8; j++)
#pragma unroll
                for (int c = 0; c < 4; c++) acc[i][j][c] = 0.f;

#pragma unroll
        for (int k = 0; k < DD; k += 16) {
            const int ca = (k >> 3) + (sub >> 1);
            unsigned aH0[4], aH1[4], aL0[4], aL1[4];
            ldsm4(aH0, smb + SM_AHI + rA0 * 256 + (((unsigned)(ca ^ (rA0 & 7))) << 4));
            ldsm4(aH1, smb + SM_AHI + rA1 * 256 + (((unsigned)(ca ^ (rA1 & 7))) << 4));
            ldsm4(aL0, smb + SM_ALO + rA0 * 256 + (((unsigned)(ca ^ (rA0 & 7))) << 4));
            ldsm4(aL1, smb + SM_ALO + rA1 * 256 + (((unsigned)(ca ^ (rA1 & 7))) << 4));
            const int cb = (k >> 3) + (sub & 1);
#pragma unroll
            for (int p = 0; p < 4; p++) {
                const int rB = n0 + 16 * p + rBo;
                const unsigned boff = (unsigned)rB * 256u + (((unsigned)(cb ^ (rB & 7))) << 4);
                unsigned bH[4], bL[4];
                ldsm4(bH, smb + SM_BHI + boff);
                mma16816(acc[0][2 * p],     aH0, bH[0], bH[1]);
                mma16816(acc[0][2 * p + 1], aH0, bH[2], bH[3]);
                mma16816(acc[1][2 * p],     aH1, bH[0], bH[1]);
                mma16816(acc[1][2 * p + 1], aH1, bH[2], bH[3]);
                mma16816(acc[0][2 * p],     aL0, bH[0], bH[1]);
                mma16816(acc[0][2 * p + 1], aL0, bH[2], bH[3]);
                mma16816(acc[1][2 * p],     aL1, bH[0], bH[1]);
                mma16816(acc[1][2 * p + 1], aL1, bH[2], bH[3]);
                ldsm4(bL, smb + SM_BLO + boff);
                mma16816(acc[0][2 * p],     aH0, bL[0], bL[1]);
                mma16816(acc[0][2 * p + 1], aH0, bL[2], bL[3]);
                mma16816(acc[1][2 * p],     aH1, bL[0], bL[1]);
                mma16816(acc[1][2 * p + 1], aH1, bL[2], bL[3]);
            }
        }

        // ---- epilogue part 1: u = silu(acc + gather), partial LN sums ----
        int tix[2][2];
        float s1v[2][2], s2v[2][2];
#pragma unroll
        for (int mt = 0; mt < 2; mt++) {
#pragma unroll
            for (int hr = 0; hr < 2; hr++) {
                const int r = m0 + 16 * mt + 8 * hr + g;
                const int gec = base + ((r < nE) ? r : 0);
                const int si = __ldg(src_idx + gec);
                const int ti = __ldg(tgt_idx + gec);
                tix[mt][hr] = ti;
                const float* gsp = g_srcP + (size_t)si * DD;
                const float* gtp = g_tgtP + (size_t)ti * DD;
                float s1 = 0.f, s2 = 0.f;
#pragma unroll
                for (int p = 0; p < 8; p++) {
                    const int c = n0 + 8 * p + 2 * q;
                    float2 a = __ldg((const float2*)(gsp + c));
                    float2 b = __ldg((const float2*)(gtp + c));
                    float u0 = silu(acc[mt][p][2 * hr]     + a.x + b.x);
                    float u1 = silu(acc[mt][p][2 * hr + 1] + a.y + b.y);
                    acc[mt][p][2 * hr] = u0;
                    acc[mt][p][2 * hr + 1] = u1;
                    s1 += u0 + u1;
                    s2 = fmaf(u0, u0, fmaf(u1, u1, s2));
                }
                s1 += __shfl_xor_sync(0xffffffffu, s1, 1);
                s2 += __shfl_xor_sync(0xffffffffu, s2, 1);
                s1 += __shfl_xor_sync(0xffffffffu, s1, 2);
                s2 += __shfl_xor_sync(0xffffffffu, s2, 2);
                s1v[mt][hr] = s1; s2v[mt][hr] = s2;
                if (q == 0)
                    ((float2*)(smem + SM_SUMS))[r * 2 + wb] = make_float2(s1, s2);
            }
        }
        __syncthreads();

        // ---- epilogue part 2: LN + residual + store + scatter-add ----
#pragma unroll
        for (int mt = 0; mt < 2; mt++) {
#pragma unroll
            for (int hr = 0; hr < 2; hr++) {
                const int r = m0 + 16 * mt + 8 * hr + g;
                if (r < nE) {
                    const int ge = base + r;
                    float2 oth = ((float2*)(smem + SM_SUMS))[r * 2 + (wb ^ 1)];
                    const float s1 = s1v[mt][hr] + oth.x;
                    const float s2 = s2v[mt][hr] + oth.y;
                    const float mean = s1 * (1.0f / 128.0f);
                    const float var  = s2 * (1.0f / 128.0f) - mean * mean;
                    const float rstd = rsqrtf(var + 1e-5f);
                    const float* er = edge + (size_t)ge * DD;
                    float* eo = edge_out + (size_t)ge * DD;
                    float* ap = g_agg + (size_t)tix[mt][hr] * DD;
#pragma unroll
                    for (int p = 0; p < 8; p++) {
                        const int c = n0 + 8 * p + 2 * q;
                        float2 res = __ldg((const float2*)(er + c));
                        float2 lg = *(const float2*)((const float*)(smem + SM_LN) + c);
                        float2 lb = *(const float2*)((const float*)(smem + SM_LN) + DD + c);
                        float2 o;
                        o.x = res.x + (acc[mt][p][2 * hr]     - mean) * rstd * lg.x + lb.x;
                        o.y = res.y + (acc[mt][p][2 * hr + 1] - mean) * rstd * lg.y + lb.y;
                        *(float2*)(eo + c) = o;
                        asm volatile("red.global.add.v2.f32 [%0], {%1,%2};"
                                     :: "l"(ap + c), "f"(o.x), "f"(o.y) : "memory");
                    }
                }
            }
        }
    }
}

// ---------------- K3: persistent fused node update (FFMA) ----------------
__global__ void __launch_bounds__(NTHR, 2)
node_out_kernel(const float* __restrict__ tgt,
                const float* __restrict__ ln_g, const float* __restrict__ ln_b,
                float* __restrict__ tgt_out) {
    extern __shared__ float sm[];
    float* ws  = sm;
    float* xs  = sm + DD * DD;
    float* lnp = xs + TILE * PITCH;
    const int tid = threadIdx.x;
    load_w(ws, g_WtV, tid);
    for (int i = tid; i < DD; i += NTHR) { lnp[i] = ln_g[i]; lnp[DD + i] = ln_b[i]; }
    const int lane = tid & 31;
    const int j0 = (lane & 15) << 3;
    const int eb = ((tid >> 5) << 3) + (lane >> 4);
    const int NT = (NN + TILE - 1) / TILE;

    for (int t = blockIdx.x; t < NT; t += gridDim.x) {
        const int base = t * TILE;
        __syncthreads();
        load_x64(xs, tgt, base, NN, tid);
        __syncthreads();
        u64 acc[4][4];
        gemm64(xs, ws, tid, acc);

        const int nR = (NN - base < TILE) ? (NN - base) : TILE;
        const float4 lg0 = *(const float4*)(lnp + j0);
        const float4 lg1 = *(const float4*)(lnp + j0 + 4);
        const float4 lb0 = *(const float4*)(lnp + DD + j0);
        const float4 lb1 = *(const float4*)(lnp + DD + j0 + 4);
#pragma unroll
        for (int i = 0; i < 4; i++) {
            const int r = eb + 2 * i;
            const int row = base + (r < nR ? r : 0);
            const float4 a0 = __ldg((const float4*)(g_aggP + (size_t)row * DD + j0));
            const float4 a1 = __ldg((const float4*)(g_aggP + (size_t)row * DD + j0) + 1);
            float2 m0 = unpack2(acc[i][0]), m1 = unpack2(acc[i][1]);
            float2 m2 = unpack2(acc[i][2]), m3 = unpack2(acc[i][3]);
            float u0 = silu(m0.x + a0.x);
            float u1 = silu(m0.y + a0.y);
            float u2 = silu(m1.x + a0.z);
            float u3 = silu(m1.y + a0.w);
            float u4 = silu(m2.x + a1.x);
            float u5 = silu(m2.y + a1.y);
            float u6 = silu(m3.x + a1.z);
            float u7 = silu(m3.y + a1.w);
            float s1 = ((u0 + u1) + (u2 + u3)) + ((u4 + u5) + (u6 + u7));
            float s2 = fmaf(u0, u0, fmaf(u1, u1, fmaf(u2, u2, fmaf(u3, u3,
                       fmaf(u4, u4, fmaf(u5, u5, fmaf(u6, u6, u7 * u7)))))));
#pragma unroll
            for (int o = 8; o > 0; o >>= 1) {
                s1 += __shfl_xor_sync(0xffffffffu, s1, o);
                s2 += __shfl_xor_sync(0xffffffffu, s2, o);
            }
            const float mean = s1 * (1.0f / 128.0f);
            const float var  = s2 * (1.0f / 128.0f) - mean * mean;
            const float rstd = rsqrtf(var + 1e-5f);
            const float* xr = xs + r * PITCH + j0;
            const float4 r0 = *(const float4*)xr;
            const float4 r1 = *(const float4*)(xr + 4);
            float4 o0, o1;
            o0.x = r0.x + (u0 - mean) * rstd * lg0.x + lb0.x;
            o0.y = r0.y + (u1 - mean) * rstd * lg0.y + lb0.y;
            o0.z = r0.z + (u2 - mean) * rstd * lg0.z + lb0.z;
            o0.w = r0.w + (u3 - mean) * rstd * lg0.w + lb0.w;
            o1.x = r1.x + (u4 - mean) * rstd * lg1.x + lb1.x;
            o1.y = r1.y + (u5 - mean) * rstd * lg1.y + lb1.y;
            o1.z = r1.z + (u6 - mean) * rstd * lg1.z + lb1.z;
            o1.w = r1.w + (u7 - mean) * rstd * lg1.w + lb1.w;
            if (r < nR) {
                *(float4*)(tgt_out + (size_t)(base + r) * DD + j0)     = o0;
                *(float4*)(tgt_out + (size_t)(base + r) * DD + j0 + 4) = o1;
            }
        }
    }
}

// ---------------- launcher ----------------
extern "C" void kernel_launch(void* const* d_in, const int* in_sizes, int n_in,
                              void* d_out, int out_size) {
    (void)in_sizes; (void)n_in; (void)out_size;
    const float* src     = (const float*)d_in[0];
    const float* tgt     = (const float*)d_in[1];
    const float* edge    = (const float*)d_in[2];
    const int*   src_idx = (const int*)d_in[3];
    const int*   tgt_idx = (const int*)d_in[4];
    const float* W_s2e   = (const float*)d_in[5];
    const float* W_t2e   = (const float*)d_in[6];
    const float* W_e2e   = (const float*)d_in[7];
    const float* W_e2t   = (const float*)d_in[8];
    const float* W_t2t   = (const float*)d_in[9];
    const float* ln1_g   = (const float*)d_in[10];
    const float* ln1_b   = (const float*)d_in[11];
    const float* ln2_g   = (const float*)d_in[12];
    const float* ln2_b   = (const float*)d_in[13];

    float* edge_out = (float*)d_out;
    float* tgt_out  = (float*)d_out + (size_t)NE * DD;

    const int SMEMP = (DD * DD + TILE * PITCH) * 4;            // 99,328 B
    const int SMEMF = (DD * DD + TILE * PITCH + 2 * DD) * 4;   // 100,352 B
    cudaFuncSetAttribute(proj_kernel,     cudaFuncAttributeMaxDynamicSharedMemorySize, SMEMP);
    cudaFuncSetAttribute(edge_kernel,     cudaFuncAttributeMaxDynamicSharedMemorySize, SM_EDGE_TOTAL);
    cudaFuncSetAttribute(node_out_kernel, cudaFuncAttributeMaxDynamicSharedMemorySize, SMEMF);

    const int GP = 296;   // 2 CTAs/SM persistent (FFMA kernels)
    const int GE = 148;   // 1 CTA/SM persistent (HMMA kernel)

    prep_kernel<<<(DD * DD + 255) / 256, 256>>>(W_s2e, W_t2e, W_e2t, W_t2t);
    zero_agg_kernel<<<1024, 256>>>();
    proj_kernel<<<GP, NTHR, SMEMP>>>(src, 0);
    proj_kernel<<<GP, NTHR, SMEMP>>>(tgt, 1);
    edge_kernel<<<GE, NTHR, SM_EDGE_TOTAL>>>(edge, src_idx, tgt_idx, W_e2e, ln1_g, ln1_b, edge_out);
    proj_kernel<<<GP, NTHR, SMEMP>>>(nullptr, 2);
    node_out_kernel<<<GP, NTHR, SMEMF>>>(tgt, ln2_g, ln2_b, tgt_out);
}

// round 12
// speedup vs baseline: 1.6064x; 1.1805x over previous
#include <cuda_runtime.h>
#include <cuda_bf16.h>

#define NN 50000
#define NE 500000
#define DD 128
#define ET 128
#define NTHR 256

#define NT_E ((NE + ET - 1) / ET)   // 3907
#define NT_P ((NN + ET - 1) / ET)   // 391

// ---- shared-memory maps (bytes) ----
// proj/edge: B hi/lo | A hi/lo | RAW fp32
#define SM_BH  0
#define SM_BL  32768
#define SM_AH  65536
#define SM_AL  98304
#define SM_RAW 131072
#define SM_LN  196608
#define SM_SUM 197632
#define SMEM_PROJ 196608
#define SMEM_EDGE 199680
// node: B1 hi/lo | B2 hi/lo | A hi/lo (no RAW)
#define SM_N_B1H 0
#define SM_N_B1L 32768
#define SM_N_B2H 65536
#define SM_N_B2L 98304
#define SM_N_AH  131072
#define SM_N_AL  163840
#define SMEM_NODE 199680

// ---------------- device scratch ----------------
__device__ float g_srcP[(size_t)NN * DD];
__device__ float g_tgtP[(size_t)NN * DD];
__device__ float g_agg [(size_t)NN * DD];
__device__ int   g_cnt[NN];
__device__ int   g_off[NN];
__device__ int   g_perm[NE];

__device__ __forceinline__ float silu(float x) { return x * (1.0f / (1.0f + __expf(-x))); }

__device__ __forceinline__ unsigned smem_u32(const void* p) {
    unsigned a;
    asm("{ .reg .u64 t; cvta.to.shared.u64 t, %1; cvt.u32.u64 %0, t; }" : "=r"(a) : "l"(p));
    return a;
}
__device__ __forceinline__ void ldsm4(unsigned r[4], unsigned addr) {
    asm volatile("ldmatrix.sync.aligned.m8n8.x4.shared.b16 {%0,%1,%2,%3}, [%4];"
                 : "=r"(r[0]), "=r"(r[1]), "=r"(r[2]), "=r"(r[3]) : "r"(addr));
}
__device__ __forceinline__ void mma16816(float c[4], const unsigned a[4],
                                         unsigned b0, unsigned b1) {
    asm volatile("mma.sync.aligned.m16n8k16.row.col.f32.bf16.bf16.f32 "
                 "{%0,%1,%2,%3}, {%4,%5,%6,%7}, {%8,%9}, {%0,%1,%2,%3};"
                 : "+f"(c[0]), "+f"(c[1]), "+f"(c[2]), "+f"(c[3])
                 : "r"(a[0]), "r"(a[1]), "r"(a[2]), "r"(a[3]), "r"(b0), "r"(b1));
}
__device__ __forceinline__ unsigned pack_bf2(__nv_bfloat16 a, __nv_bfloat16 b) {
    __nv_bfloat162 t = __halves2bfloat162(a, b);
    return *reinterpret_cast<unsigned*>(&t);
}
__device__ __forceinline__ void cp_commit() { asm volatile("cp.async.commit_group;" ::: "memory"); }
__device__ __forceinline__ void cp_wait0()  { asm volatile("cp.async.wait_group 0;" ::: "memory"); }

// store 4 fp32 as bf16 hi/lo into swizzled tile: row pitch 256B, 16B-chunk XOR (row&7)
__device__ __forceinline__ void store_hilo(char* smem, int offH, int offL,
                                           int row, int c0, float4 v) {
    unsigned chunk = ((unsigned)c0 >> 3) ^ ((unsigned)row & 7u);
    unsigned off = (unsigned)row * 256u + chunk * 16u + ((unsigned)c0 & 7u) * 2u;
    __nv_bfloat16 hx = __float2bfloat16(v.x);
    __nv_bfloat16 hy = __float2bfloat16(v.y);
    __nv_bfloat16 hz = __float2bfloat16(v.z);
    __nv_bfloat16 hw = __float2bfloat16(v.w);
    __nv_bfloat16 lx = __float2bfloat16(v.x - __bfloat162float(hx));
    __nv_bfloat16 ly = __float2bfloat16(v.y - __bfloat162float(hy));
    __nv_bfloat16 lz = __float2bfloat16(v.z - __bfloat162float(hz));
    __nv_bfloat16 lw = __float2bfloat16(v.w - __bfloat162float(hw));
    *(uint2*)(smem + offH + off) = make_uint2(pack_bf2(hx, hy), pack_bf2(hz, hw));
    *(uint2*)(smem + offL + off) = make_uint2(pack_bf2(lx, ly), pack_bf2(lz, lw));
}

// read back exact value (hi+lo) of 2 consecutive cols from swizzled tiles
__device__ __forceinline__ float2 smem_hilo2(const char* smem, int offH, int offL, int r, int c) {
    unsigned chunk = ((unsigned)c >> 3) ^ ((unsigned)r & 7u);
    unsigned off = (unsigned)r * 256u + chunk * 16u + ((unsigned)c & 7u) * 2u;
    unsigned h = *(const unsigned*)(smem + offH + off);
    unsigned l = *(const unsigned*)(smem + offL + off);
    __nv_bfloat162 hb = *reinterpret_cast<__nv_bfloat162*>(&h);
    __nv_bfloat162 lb = *reinterpret_cast<__nv_bfloat162*>(&l);
    return make_float2(__bfloat162float(hb.x) + __bfloat162float(lb.x),
                       __bfloat162float(hb.y) + __bfloat162float(lb.y));
}

// convert B = W[n][k] (global) into bf16 hi/lo swizzled tile
__device__ __forceinline__ void convert_B(char* smem, int offH, int offL,
                                          const float* __restrict__ W, int tid) {
#pragma unroll
    for (int it = 0; it < 16; it++) {
        int i = tid + it * NTHR;
        int n = i >> 5, c0 = (i & 31) << 2;
        float4 v = __ldg((const float4*)(W + (size_t)n * DD + c0));
        store_hilo(smem, offH, offL, n, c0, v);
    }
}

// cp.async stage of a raw fp32 tile (zero-fill OOB rows), commits a group
__device__ __forceinline__ void stage_raw(char* smem, const float* __restrict__ g,
                                          int base, int M, int tid) {
#pragma unroll
    for (int it = 0; it < 16; it++) {
        int i = tid + it * NTHR;
        int r = i >> 5, c0 = (i & 31) << 2;
        char* dstp = smem + SM_RAW + r * 512 + c0 * 4;
        if (base + r < M) {
            unsigned dst = smem_u32(dstp);
            const float* src = g + (size_t)(base + r) * DD + c0;
            asm volatile("cp.async.cg.shared.global [%0], [%1], 16;" :: "r"(dst), "l"(src));
        } else {
            *(float4*)dstp = make_float4(0.f, 0.f, 0.f, 0.f);
        }
    }
    cp_commit();
}

// convert RAW fp32 smem tile -> bf16 hi/lo tiles
__device__ __forceinline__ void convert_A(char* smem, int offH, int offL, int tid) {
#pragma unroll
    for (int it = 0; it < 16; it++) {
        int i = tid + it * NTHR;
        int r = i >> 5, c0 = (i & 31) << 2;
        float4 v = *(const float4*)(smem + SM_RAW + r * 512 + c0 * 4);
        store_hilo(smem, offH, offL, r, c0, v);
    }
}

// direct global -> bf16 hi/lo (no cp.async; used by node kernel)
__device__ __forceinline__ void convert_A_direct(char* smem, int offH, int offL,
                                                 const float* __restrict__ g,
                                                 int base, int M, int tid) {
#pragma unroll
    for (int it = 0; it < 16; it++) {
        int i = tid + it * NTHR;
        int r = i >> 5, c0 = (i & 31) << 2;
        float4 v = make_float4(0.f, 0.f, 0.f, 0.f);
        if (base + r < M) v = __ldg((const float4*)(g + (size_t)(base + r) * DD + c0));
        store_hilo(smem, offH, offL, r, c0, v);
    }
}

// ---- bf16x3 HMMA: 128x128 tile, warp = m32 x n64; acc[mt][j][.] col = n0+8j ----
__device__ __forceinline__ void mma_tile(unsigned smb, int offAH, int offAL,
                                         int offBH, int offBL,
                                         int rA0, int rA1, int rBo, int n0, int sub,
                                         float (&acc)[2][8][4]) {
#pragma unroll
    for (int k = 0; k < DD; k += 16) {
        const int ca = (k >> 3) + (sub >> 1);
        unsigned aH0[4], aH1[4], aL0[4], aL1[4];
        ldsm4(aH0, smb + offAH + rA0 * 256 + (((unsigned)(ca ^ (rA0 & 7))) << 4));
        ldsm4(aH1, smb + offAH + rA1 * 256 + (((unsigned)(ca ^ (rA1 & 7))) << 4));
        ldsm4(aL0, smb + offAL + rA0 * 256 + (((unsigned)(ca ^ (rA0 & 7))) << 4));
        ldsm4(aL1, smb + offAL + rA1 * 256 + (((unsigned)(ca ^ (rA1 & 7))) << 4));
        const int cb = (k >> 3) + (sub & 1);
#pragma unroll
        for (int p = 0; p < 4; p++) {
            const int rB = n0 + 16 * p + rBo;
            const unsigned boff = (unsigned)rB * 256u + (((unsigned)(cb ^ (rB & 7))) << 4);
            unsigned bH[4], bL[4];
            ldsm4(bH, smb + offBH + boff);
            mma16816(acc[0][2 * p],     aH0, bH[0], bH[1]);
            mma16816(acc[0][2 * p + 1], aH0, bH[2], bH[3]);
            mma16816(acc[1][2 * p],     aH1, bH[0], bH[1]);
            mma16816(acc[1][2 * p + 1], aH1, bH[2], bH[3]);
            mma16816(acc[0][2 * p],     aL0, bH[0], bH[1]);
            mma16816(acc[0][2 * p + 1], aL0, bH[2], bH[3]);
            mma16816(acc[1][2 * p],     aL1, bH[0], bH[1]);
            mma16816(acc[1][2 * p + 1], aL1, bH[2], bH[3]);
            ldsm4(bL, smb + offBL + boff);
            mma16816(acc[0][2 * p],     aH0, bL[0], bL[1]);
            mma16816(acc[0][2 * p + 1], aH0, bL[2], bL[3]);
            mma16816(acc[1][2 * p],     aH1, bL[0], bL[1]);
            mma16816(acc[1][2 * p + 1], aH1, bL[2], bL[3]);
        }
    }
}

// ================= sort-based segment-sum machinery =================
__global__ void zero_cnt_kernel() {
    int i = blockIdx.x * blockDim.x + threadIdx.x;
    if (i < NN) g_cnt[i] = 0;
}
__global__ void hist_kernel(const int* __restrict__ tgt_idx) {
    int e = blockIdx.x * blockDim.x + threadIdx.x;
    if (e < NE) atomicAdd(&g_cnt[tgt_idx[e]], 1);
}
__global__ void scan_kernel() {
    __shared__ int wsums[32];
    const int tid = threadIdx.x, lane = tid & 31, wid = tid >> 5;
    int run = 0;
    for (int base = 0; base < NN; base += 1024) {
        int idx = base + tid;
        int v = (idx < NN) ? g_cnt[idx] : 0;
        int x = v;
#pragma unroll
        for (int o = 1; o < 32; o <<= 1) {
            int y = __shfl_up_sync(0xffffffffu, x, o);
            if (lane >= o) x += y;
        }
        if (lane == 31) wsums[wid] = x;
        __syncthreads();
        if (wid == 0) {
            int s = wsums[lane];
#pragma unroll
            for (int o = 1; o < 32; o <<= 1) {
                int y = __shfl_up_sync(0xffffffffu, s, o);
                if (lane >= o) s += y;
            }
            wsums[lane] = s;
        }
        __syncthreads();
        int pref = (wid > 0) ? wsums[wid - 1] : 0;
        if (idx < NN) g_off[idx] = run + pref + x - v;
        run += wsums[31];
        __syncthreads();
    }
}
__global__ void scatter_kernel(const int* __restrict__ tgt_idx) {
    int e = blockIdx.x * blockDim.x + threadIdx.x;
    if (e < NE) {
        int slot = atomicAdd(&g_off[tgt_idx[e]], 1);
        g_perm[slot] = e;
    }
}
// warp-per-node segment sum: g_agg[n] = sum of edge_out rows with tgt==n
__global__ void agg_kernel(const float* __restrict__ edge_out) {
    int w = (blockIdx.x * blockDim.x + threadIdx.x) >> 5;
    int lane = threadIdx.x & 31;
    if (w >= NN) return;
    int end = g_off[w];                 // post-scatter == segment end
    int beg = end - g_cnt[w];
    float4 a = make_float4(0.f, 0.f, 0.f, 0.f);
    for (int j = beg; j < end; j++) {
        int e = g_perm[j];
        float4 v = __ldg((const float4*)(edge_out + (size_t)e * DD) + lane);
        a.x += v.x; a.y += v.y; a.z += v.z; a.w += v.w;
    }
    ((float4*)(g_agg + (size_t)w * DD))[lane] = a;
}

// ================= K1: fused src+tgt projection (HMMA) =================
__device__ __forceinline__ void proj_phase(char* smem, unsigned smb,
                                           const float* __restrict__ X,
                                           const float* __restrict__ W,
                                           float* __restrict__ O, int tid) {
    convert_B(smem, SM_BH, SM_BL, W, tid);
    const int wid = tid >> 5, lane = tid & 31;
    const int wa = wid & 3, h = wid >> 2;
    const int m0 = wa * 32, n0 = h * 64;
    const int g = lane >> 2, q = lane & 3;
    const int within = lane & 7, sub = lane >> 3;
    const int rA0 = m0 + within + ((sub & 1) << 3);
    const int rA1 = rA0 + 16;
    const int rBo = within + ((sub >> 1) << 3);

    stage_raw(smem, X, blockIdx.x * ET, NN, tid);
    __syncthreads();   // B ready too
    for (int t = blockIdx.x; t < NT_P; t += gridDim.x) {
        const int base = t * ET;
        cp_wait0();
        __syncthreads();
        convert_A(smem, SM_AH, SM_AL, tid);
        __syncthreads();
        const int tn = t + gridDim.x;
        if (tn < NT_P) stage_raw(smem, X, tn * ET, NN, tid);
        else cp_commit();

        float acc[2][8][4];
#pragma unroll
        for (int i = 0; i < 2; i++)
#pragma unroll
            for (int j = 0; j < 8; j++)
#pragma unroll
                for (int c = 0; c < 4; c++) acc[i][j][c] = 0.f;
        mma_tile(smb, SM_AH, SM_AL, SM_BH, SM_BL, rA0, rA1, rBo, n0, sub, acc);

        const int nR = (NN - base < ET) ? (NN - base) : ET;
#pragma unroll
        for (int mt = 0; mt < 2; mt++) {
#pragma unroll
            for (int hr = 0; hr < 2; hr++) {
                const int r = m0 + 16 * mt + 8 * hr + g;
                if (r < nR) {
                    float* o = O + (size_t)(base + r) * DD;
#pragma unroll
                    for (int p = 0; p < 8; p++) {
                        const int c = n0 + 8 * p + 2 * q;
                        *(float2*)(o + c) = make_float2(acc[mt][p][2 * hr],
                                                        acc[mt][p][2 * hr + 1]);
                    }
                }
            }
        }
    }
    __syncthreads();   // drain before caller overwrites B
}

__global__ void __launch_bounds__(NTHR, 1)
proj_kernel(const float* __restrict__ src, const float* __restrict__ tgt,
            const float* __restrict__ Ws2e, const float* __restrict__ Wt2e) {
    extern __shared__ __align__(128) char smem[];
    const unsigned smb = smem_u32(smem);
    proj_phase(smem, smb, src, Ws2e, g_srcP, threadIdx.x);
    proj_phase(smem, smb, tgt, Wt2e, g_tgtP, threadIdx.x);
}

// ================= K2: fused edge update (HMMA, no atomics) =================
__global__ void __launch_bounds__(NTHR, 1)
edge_kernel(const float* __restrict__ edge,
            const int* __restrict__ src_idx, const int* __restrict__ tgt_idx,
            const float* __restrict__ We2e,
            const float* __restrict__ ln_g, const float* __restrict__ ln_b,
            float* __restrict__ edge_out) {
    extern __shared__ __align__(128) char smem[];
    const unsigned smb = smem_u32(smem);
    const int tid = threadIdx.x;
    const int wid = tid >> 5, lane = tid & 31;

    convert_B(smem, SM_BH, SM_BL, We2e, tid);
    for (int i = tid; i < DD; i += NTHR) {
        ((float*)(smem + SM_LN))[i] = ln_g[i];
        ((float*)(smem + SM_LN))[DD + i] = ln_b[i];
    }

    const int wa = wid & 3, h = wid >> 2;
    const int m0 = wa * 32, n0 = h * 64;
    const int g = lane >> 2, q = lane & 3;
    const int within = lane & 7, sub = lane >> 3;
    const int rA0 = m0 + within + ((sub & 1) << 3);
    const int rA1 = rA0 + 16;
    const int rBo = within + ((sub >> 1) << 3);

    stage_raw(smem, edge, blockIdx.x * ET, NE, tid);
    __syncthreads();

    for (int t = blockIdx.x; t < NT_E; t += gridDim.x) {
        const int base = t * ET;
        const int nE = (NE - base < ET) ? (NE - base) : ET;
        cp_wait0();
        __syncthreads();                    // raw ready; prev-tile smem readers done
        convert_A(smem, SM_AH, SM_AL, tid);
        __syncthreads();
        const int tn = t + gridDim.x;
        if (tn < NT_E) stage_raw(smem, edge, tn * ET, NE, tid);
        else cp_commit();

        float acc[2][8][4];
#pragma unroll
        for (int i = 0; i < 2; i++)
#pragma unroll
            for (int j = 0; j < 8; j++)
#pragma unroll
                for (int c = 0; c < 4; c++) acc[i][j][c] = 0.f;
        mma_tile(smb, SM_AH, SM_AL, SM_BH, SM_BL, rA0, rA1, rBo, n0, sub, acc);

        // ---- epilogue part 1: u = silu(acc + srcP[s] + tgtP[t]); partial LN sums ----
        float s1v[2][2], s2v[2][2];
#pragma unroll
        for (int mt = 0; mt < 2; mt++) {
#pragma unroll
            for (int hr = 0; hr < 2; hr++) {
                const int r = m0 + 16 * mt + 8 * hr + g;
                const int gec = base + ((r < nE) ? r : 0);
                const int si = __ldg(src_idx + gec);
                const int ti = __ldg(tgt_idx + gec);
                const float* gsp = g_srcP + (size_t)si * DD;
                const float* gtp = g_tgtP + (size_t)ti * DD;
                float s1 = 0.f, s2 = 0.f;
#pragma unroll
                for (int p = 0; p < 8; p++) {
                    const int c = n0 + 8 * p + 2 * q;
                    float2 a = __ldg((const float2*)(gsp + c));
                    float2 b = __ldg((const float2*)(gtp + c));
                    float u0 = silu(acc[mt][p][2 * hr]     + a.x + b.x);
                    float u1 = silu(acc[mt][p][2 * hr + 1] + a.y + b.y);
                    acc[mt][p][2 * hr] = u0;
                    acc[mt][p][2 * hr + 1] = u1;
                    s1 += u0 + u1;
                    s2 = fmaf(u0, u0, fmaf(u1, u1, s2));
                }
                s1 += __shfl_xor_sync(0xffffffffu, s1, 1);
                s2 += __shfl_xor_sync(0xffffffffu, s2, 1);
                s1 += __shfl_xor_sync(0xffffffffu, s1, 2);
                s2 += __shfl_xor_sync(0xffffffffu, s2, 2);
                s1v[mt][hr] = s1; s2v[mt][hr] = s2;
                if (q == 0)
                    ((float2*)(smem + SM_SUM))[r * 2 + h] = make_float2(s1, s2);
            }
        }
        __syncthreads();

        // ---- epilogue part 2: LN + residual (from smem hi+lo) + store ----
#pragma unroll
        for (int mt = 0; mt < 2; mt++) {
#pragma unroll
            for (int hr = 0; hr < 2; hr++) {
                const int r = m0 + 16 * mt + 8 * hr + g;
                if (r < nE) {
                    const int ge = base + r;
                    float2 oth = ((float2*)(smem + SM_SUM))[r * 2 + (h ^ 1)];
                    const float s1 = s1v[mt][hr] + oth.x;
                    const float s2 = s2v[mt][hr] + oth.y;
                    const float mean = s1 * (1.0f / 128.0f);
                    const float var  = s2 * (1.0f / 128.0f) - mean * mean;
                    const float rstd = rsqrtf(var + 1e-5f);
                    float* eo = edge_out + (size_t)ge * DD;
#pragma unroll
                    for (int p = 0; p < 8; p++) {
                        const int c = n0 + 8 * p + 2 * q;
                        float2 res = smem_hilo2(smem, SM_AH, SM_AL, r, c);
                        float2 lg = *(const float2*)((const float*)(smem + SM_LN) + c);
                        float2 lb = *(const float2*)((const float*)(smem + SM_LN) + DD + c);
                        float2 o;
                        o.x = res.x + (acc[mt][p][2 * hr]     - mean) * rstd * lg.x + lb.x;
                        o.y = res.y + (acc[mt][p][2 * hr + 1] - mean) * rstd * lg.y + lb.y;
                        *(float2*)(eo + c) = o;
                    }
                }
            }
        }
    }
}

// ================= K3: fused node update (dual HMMA) =================
// msg = agg@W_e2t^T + tgt@W_t2t^T; tgt_out = tgt + LN(silu(msg))
__global__ void __launch_bounds__(NTHR, 1)
node_kernel(const float* __restrict__ tgt,
            const float* __restrict__ We2t, const float* __restrict__ Wt2t,
            const float* __restrict__ ln_g, const float* __restrict__ ln_b,
            float* __restrict__ tgt_out) {
    extern __shared__ __align__(128) char smem[];
    const unsigned smb = smem_u32(smem);
    const int tid = threadIdx.x;
    const int wid = tid >> 5, lane = tid & 31;

    convert_B(smem, SM_N_B1H, SM_N_B1L, We2t, tid);
    convert_B(smem, SM_N_B2H, SM_N_B2L, Wt2t, tid);
    for (int i = tid; i < DD; i += NTHR) {
        ((float*)(smem + SM_LN))[i] = ln_g[i];
        ((float*)(smem + SM_LN))[DD + i] = ln_b[i];
    }

    const int wa = wid & 3, h = wid >> 2;
    const int m0 = wa * 32, n0 = h * 64;
    const int g = lane >> 2, q = lane & 3;
    const int within = lane & 7, sub = lane >> 3;
    const int rA0 = m0 + within + ((sub & 1) << 3);
    const int rA1 = rA0 + 16;
    const int rBo = within + ((sub >> 1) << 3);

    for (int t = blockIdx.x; t < NT_P; t += gridDim.x) {
        const int base = t * ET;
        const int nR = (NN - base < ET) ? (NN - base) : ET;
        __syncthreads();                           // prev-tile smem readers done
        convert_A_direct(smem, SM_N_AH, SM_N_AL, g_agg, base, NN, tid);
        __syncthreads();

        float acc[2][8][4];
#pragma unroll
        for (int i = 0; i < 2; i++)
#pragma unroll
            for (int j = 0; j < 8; j++)
#pragma unroll
                for (int c = 0; c < 4; c++) acc[i][j][c] = 0.f;
        mma_tile(smb, SM_N_AH, SM_N_AL, SM_N_B1H, SM_N_B1L, rA0, rA1, rBo, n0, sub, acc);
        __syncthreads();                           // done reading agg tile
        convert_A_direct(smem, SM_N_AH, SM_N_AL, tgt, base, NN, tid);
        __syncthreads();
        mma_tile(smb, SM_N_AH, SM_N_AL, SM_N_B2H, SM_N_B2L, rA0, rA1, rBo, n0, sub, acc);

        // epilogue: u = silu(acc); LN; residual tgt (from smem hi+lo); store
        float s1v[2][2], s2v[2][2];
#pragma unroll
        for (int mt = 0; mt < 2; mt++) {
#pragma unroll
            for (int hr = 0; hr < 2; hr++) {
                const int r = m0 + 16 * mt + 8 * hr + g;
                float s1 = 0.f, s2 = 0.f;
#pragma unroll
                for (int p = 0; p < 8; p++) {
                    float u0 = silu(acc[mt][p][2 * hr]);
                    float u1 = silu(acc[mt][p][2 * hr + 1]);
                    acc[mt][p][2 * hr] = u0;
                    acc[mt][p][2 * hr + 1] = u1;
                    s1 += u0 + u1;
                    s2 = fmaf(u0, u0, fmaf(u1, u1, s2));
                }
                s1 += __shfl_xor_sync(0xffffffffu, s1, 1);
                s2 += __shfl_xor_sync(0xffffffffu, s2, 1);
                s1 += __shfl_xor_sync(0xffffffffu, s1, 2);
                s2 += __shfl_xor_sync(0xffffffffu, s2, 2);
                s1v[mt][hr] = s1; s2v[mt][hr] = s2;
                if (q == 0)
                    ((float2*)(smem + SM_SUM))[r * 2 + h] = make_float2(s1, s2);
            }
        }
        __syncthreads();
#pragma unroll
        for (int mt = 0; mt < 2; mt++) {
#pragma unroll
            for (int hr = 0; hr < 2; hr++) {
                const int r = m0 + 16 * mt + 8 * hr + g;
                if (r < nR) {
                    float2 oth = ((float2*)(smem + SM_SUM))[r * 2 + (h ^ 1)];
                    const float s1 = s1v[mt][hr] + oth.x;
                    const float s2 = s2v[mt][hr] + oth.y;
                    const float mean = s1 * (1.0f / 128.0f);
                    const float var  = s2 * (1.0f / 128.0f) - mean * mean;
                    const float rstd = rsqrtf(var + 1e-5f);
                    float* o = tgt_out + (size_t)(base + r) * DD;
#pragma unroll
                    for (int p = 0; p < 8; p++) {
                        const int c = n0 + 8 * p + 2 * q;
                        float2 res = smem_hilo2(smem, SM_N_AH, SM_N_AL, r, c);
                        float2 lg = *(const float2*)((const float*)(smem + SM_LN) + c);
                        float2 lb = *(const float2*)((const float*)(smem + SM_LN) + DD + c);
                        float2 ov;
                        ov.x = res.x + (acc[mt][p][2 * hr]     - mean) * rstd * lg.x + lb.x;
                        ov.y = res.y + (acc[mt][p][2 * hr + 1] - mean) * rstd * lg.y + lb.y;
                        *(float2*)(o + c) = ov;
                    }
                }
            }
        }
    }
}

// ---------------- launcher ----------------
extern "C" void kernel_launch(void* const* d_in, const int* in_sizes, int n_in,
                              void* d_out, int out_size) {
    (void)in_sizes; (void)n_in; (void)out_size;
    const float* src     = (const float*)d_in[0];
    const float* tgt     = (const float*)d_in[1];
    const float* edge    = (const float*)d_in[2];
    const int*   src_idx = (const int*)d_in[3];
    const int*   tgt_idx = (const int*)d_in[4];
    const float* W_s2e   = (const float*)d_in[5];
    const float* W_t2e   = (const float*)d_in[6];
    const float* W_e2e   = (const float*)d_in[7];
    const float* W_e2t   = (const float*)d_in[8];
    const float* W_t2t   = (const float*)d_in[9];
    const float* ln1_g   = (const float*)d_in[10];
    const float* ln1_b   = (const float*)d_in[11];
    const float* ln2_g   = (const float*)d_in[12];
    const float* ln2_b   = (const float*)d_in[13];

    float* edge_out = (float*)d_out;
    float* tgt_out  = (float*)d_out + (size_t)NE * DD;

    cudaFuncSetAttribute(proj_kernel, cudaFuncAttributeMaxDynamicSharedMemorySize, SMEM_PROJ);
    cudaFuncSetAttribute(edge_kernel, cudaFuncAttributeMaxDynamicSharedMemorySize, SMEM_EDGE);
    cudaFuncSetAttribute(node_kernel, cudaFuncAttributeMaxDynamicSharedMemorySize, SMEM_NODE);

    const int GP = 148;
    // launch order chosen so ncu (-s 5 -c 1) captures launch #6 = edge_kernel
    zero_cnt_kernel<<<(NN + 1023) / 1024, 1024>>>();                     // 1
    hist_kernel<<<(NE + 1023) / 1024, 1024>>>(tgt_idx);                  // 2
    scan_kernel<<<1, 1024>>>();                                          // 3
    scatter_kernel<<<(NE + 1023) / 1024, 1024>>>(tgt_idx);               // 4
    proj_kernel<<<GP, NTHR, SMEM_PROJ>>>(src, tgt, W_s2e, W_t2e);        // 5
    edge_kernel<<<GP, NTHR, SMEM_EDGE>>>(edge, src_idx, tgt_idx, W_e2e,
                                         ln1_g, ln1_b, edge_out);        // 6  <- profiled
    agg_kernel<<<(NN * 32 + 255) / 256, 256>>>(edge_out);                // 7
    node_kernel<<<GP, NTHR, SMEM_NODE>>>(tgt, W_e2t, W_t2t,
                                         ln2_g, ln2_b, tgt_out);         // 8
}

// round 13
// speedup vs baseline: 2.0655x; 1.2858x over previous
#include <cuda_runtime.h>
#include <cuda_bf16.h>

#define NN 50000
#define NE 500000
#define DD 128
#define ET 128
#define NTHR 512

#define NT_E ((NE + ET - 1) / ET)   // 3907
#define NT_P ((NN + ET - 1) / ET)   // 391

// ---- shared-memory maps (bytes) ----
// proj/edge: B hi/lo | A hi/lo | RAW fp32
#define SM_BH  0
#define SM_BL  32768
#define SM_AH  65536
#define SM_AL  98304
#define SM_RAW 131072
#define SM_LN  196608
#define SM_SUM 197632                 // 128 rows x 4 quarters x float2 = 4096 B
#define SMEM_PROJ 196608
#define SMEM_EDGE 201728
// node: B1 hi/lo | B2 hi/lo | A hi/lo (no RAW)
#define SM_N_B1H 0
#define SM_N_B1L 32768
#define SM_N_B2H 65536
#define SM_N_B2L 98304
#define SM_N_AH  131072
#define SM_N_AL  163840
#define SMEM_NODE 201728

// ---------------- device scratch ----------------
__device__ float g_srcP[(size_t)NN * DD];
__device__ float g_tgtP[(size_t)NN * DD];
__device__ float g_agg [(size_t)NN * DD];
__device__ int   g_cnt[NN];
__device__ int   g_off[NN];
__device__ int   g_perm[NE];

__device__ __forceinline__ float silu(float x) { return x * (1.0f / (1.0f + __expf(-x))); }

__device__ __forceinline__ unsigned smem_u32(const void* p) {
    unsigned a;
    asm("{ .reg .u64 t; cvta.to.shared.u64 t, %1; cvt.u32.u64 %0, t; }" : "=r"(a) : "l"(p));
    return a;
}
__device__ __forceinline__ void ldsm4(unsigned r[4], unsigned addr) {
    asm volatile("ldmatrix.sync.aligned.m8n8.x4.shared.b16 {%0,%1,%2,%3}, [%4];"
                 : "=r"(r[0]), "=r"(r[1]), "=r"(r[2]), "=r"(r[3]) : "r"(addr));
}
__device__ __forceinline__ void mma16816(float c[4], const unsigned a[4],
                                         unsigned b0, unsigned b1) {
    asm volatile("mma.sync.aligned.m16n8k16.row.col.f32.bf16.bf16.f32 "
                 "{%0,%1,%2,%3}, {%4,%5,%6,%7}, {%8,%9}, {%0,%1,%2,%3};"
                 : "+f"(c[0]), "+f"(c[1]), "+f"(c[2]), "+f"(c[3])
                 : "r"(a[0]), "r"(a[1]), "r"(a[2]), "r"(a[3]), "r"(b0), "r"(b1));
}
__device__ __forceinline__ unsigned pack_bf2(__nv_bfloat16 a, __nv_bfloat16 b) {
    __nv_bfloat162 t = __halves2bfloat162(a, b);
    return *reinterpret_cast<unsigned*>(&t);
}
__device__ __forceinline__ void cp_commit() { asm volatile("cp.async.commit_group;" ::: "memory"); }
__device__ __forceinline__ void cp_wait0()  { asm volatile("cp.async.wait_group 0;" ::: "memory"); }

// store 4 fp32 as bf16 hi/lo into swizzled tile: row pitch 256B, 16B-chunk XOR (row&7)
__device__ __forceinline__ void store_hilo(char* smem, int offH, int offL,
                                           int row, int c0, float4 v) {
    unsigned chunk = ((unsigned)c0 >> 3) ^ ((unsigned)row & 7u);
    unsigned off = (unsigned)row * 256u + chunk * 16u + ((unsigned)c0 & 7u) * 2u;
    __nv_bfloat16 hx = __float2bfloat16(v.x);
    __nv_bfloat16 hy = __float2bfloat16(v.y);
    __nv_bfloat16 hz = __float2bfloat16(v.z);
    __nv_bfloat16 hw = __float2bfloat16(v.w);
    __nv_bfloat16 lx = __float2bfloat16(v.x - __bfloat162float(hx));
    __nv_bfloat16 ly = __float2bfloat16(v.y - __bfloat162float(hy));
    __nv_bfloat16 lz = __float2bfloat16(v.z - __bfloat162float(hz));
    __nv_bfloat16 lw = __float2bfloat16(v.w - __bfloat162float(hw));
    *(uint2*)(smem + offH + off) = make_uint2(pack_bf2(hx, hy), pack_bf2(hz, hw));
    *(uint2*)(smem + offL + off) = make_uint2(pack_bf2(lx, ly), pack_bf2(lz, lw));
}

// read back exact value (hi+lo) of 2 consecutive cols from swizzled tiles
__device__ __forceinline__ float2 smem_hilo2(const char* smem, int offH, int offL, int r, int c) {
    unsigned chunk = ((unsigned)c >> 3) ^ ((unsigned)r & 7u);
    unsigned off = (unsigned)r * 256u + chunk * 16u + ((unsigned)c & 7u) * 2u;
    unsigned h = *(const unsigned*)(smem + offH + off);
    unsigned l = *(const unsigned*)(smem + offL + off);
    __nv_bfloat162 hb = *reinterpret_cast<__nv_bfloat162*>(&h);
    __nv_bfloat162 lb = *reinterpret_cast<__nv_bfloat162*>(&l);
    return make_float2(__bfloat162float(hb.x) + __bfloat162float(lb.x),
                       __bfloat162float(hb.y) + __bfloat162float(lb.y));
}

// convert B = W[n][k] (global) into bf16 hi/lo swizzled tile
__device__ __forceinline__ void convert_B(char* smem, int offH, int offL,
                                          const float* __restrict__ W, int tid) {
#pragma unroll
    for (int it = 0; it < 4096 / NTHR; it++) {
        int i = tid + it * NTHR;
        int n = i >> 5, c0 = (i & 31) << 2;
        float4 v = __ldg((const float4*)(W + (size_t)n * DD + c0));
        store_hilo(smem, offH, offL, n, c0, v);
    }
}

// cp.async stage of a raw fp32 tile (zero-fill OOB rows), commits a group
__device__ __forceinline__ void stage_raw(char* smem, const float* __restrict__ g,
                                          int base, int M, int tid) {
#pragma unroll
    for (int it = 0; it < 4096 / NTHR; it++) {
        int i = tid + it * NTHR;
        int r = i >> 5, c0 = (i & 31) << 2;
        char* dstp = smem + SM_RAW + r * 512 + c0 * 4;
        if (base + r < M) {
            unsigned dst = smem_u32(dstp);
            const float* src = g + (size_t)(base + r) * DD + c0;
            asm volatile("cp.async.cg.shared.global [%0], [%1], 16;" :: "r"(dst), "l"(src));
        } else {
            *(float4*)dstp = make_float4(0.f, 0.f, 0.f, 0.f);
        }
    }
    cp_commit();
}

// convert RAW fp32 smem tile -> bf16 hi/lo tiles
__device__ __forceinline__ void convert_A(char* smem, int offH, int offL, int tid) {
#pragma unroll
    for (int it = 0; it < 4096 / NTHR; it++) {
        int i = tid + it * NTHR;
        int r = i >> 5, c0 = (i & 31) << 2;
        float4 v = *(const float4*)(smem + SM_RAW + r * 512 + c0 * 4);
        store_hilo(smem, offH, offL, r, c0, v);
    }
}

// direct global -> bf16 hi/lo (node kernel)
__device__ __forceinline__ void convert_A_direct(char* smem, int offH, int offL,
                                                 const float* __restrict__ g,
                                                 int base, int M, int tid) {
#pragma unroll
    for (int it = 0; it < 4096 / NTHR; it++) {
        int i = tid + it * NTHR;
        int r = i >> 5, c0 = (i & 31) << 2;
        float4 v = make_float4(0.f, 0.f, 0.f, 0.f);
        if (base + r < M) v = __ldg((const float4*)(g + (size_t)(base + r) * DD + c0));
        store_hilo(smem, offH, offL, r, c0, v);
    }
}

// ---- bf16x3 HMMA: 128x128 tile, 16 warps, warp = m32 x n32 ----
// acc[mt][j][.]: row block mt (16 rows), col group j (8 cols at n0+8j)
__device__ __forceinline__ void mma_tile(unsigned smb, int offAH, int offAL,
                                         int offBH, int offBL,
                                         int rA0, int rA1, int rBo, int n0, int sub,
                                         float (&acc)[2][4][4]) {
#pragma unroll
    for (int k = 0; k < DD; k += 16) {
        const int ca = (k >> 3) + (sub >> 1);
        unsigned aH0[4], aH1[4], aL0[4], aL1[4];
        ldsm4(aH0, smb + offAH + rA0 * 256 + (((unsigned)(ca ^ (rA0 & 7))) << 4));
        ldsm4(aH1, smb + offAH + rA1 * 256 + (((unsigned)(ca ^ (rA1 & 7))) << 4));
        ldsm4(aL0, smb + offAL + rA0 * 256 + (((unsigned)(ca ^ (rA0 & 7))) << 4));
        ldsm4(aL1, smb + offAL + rA1 * 256 + (((unsigned)(ca ^ (rA1 & 7))) << 4));
        const int cb = (k >> 3) + (sub & 1);
#pragma unroll
        for (int p = 0; p < 2; p++) {
            const int rB = n0 + 16 * p + rBo;
            const unsigned boff = (unsigned)rB * 256u + (((unsigned)(cb ^ (rB & 7))) << 4);
            unsigned bH[4], bL[4];
            ldsm4(bH, smb + offBH + boff);
            mma16816(acc[0][2 * p],     aH0, bH[0], bH[1]);
            mma16816(acc[0][2 * p + 1], aH0, bH[2], bH[3]);
            mma16816(acc[1][2 * p],     aH1, bH[0], bH[1]);
            mma16816(acc[1][2 * p + 1], aH1, bH[2], bH[3]);
            mma16816(acc[0][2 * p],     aL0, bH[0], bH[1]);
            mma16816(acc[0][2 * p + 1], aL0, bH[2], bH[3]);
            mma16816(acc[1][2 * p],     aL1, bH[0], bH[1]);
            mma16816(acc[1][2 * p + 1], aL1, bH[2], bH[3]);
            ldsm4(bL, smb + offBL + boff);
            mma16816(acc[0][2 * p],     aH0, bL[0], bL[1]);
            mma16816(acc[0][2 * p + 1], aH0, bL[2], bL[3]);
            mma16816(acc[1][2 * p],     aH1, bL[0], bL[1]);
            mma16816(acc[1][2 * p + 1], aH1, bL[2], bL[3]);
        }
    }
}

// ================= sort-based segment-sum machinery =================
__global__ void zero_cnt_kernel() {
    int i = blockIdx.x * blockDim.x + threadIdx.x;
    if (i < NN) g_cnt[i] = 0;
}
__global__ void hist_kernel(const int* __restrict__ tgt_idx) {
    int e = blockIdx.x * blockDim.x + threadIdx.x;
    if (e < NE) atomicAdd(&g_cnt[tgt_idx[e]], 1);
}
__global__ void scan_kernel() {
    __shared__ int wsums[32];
    const int tid = threadIdx.x, lane = tid & 31, wid = tid >> 5;
    int run = 0;
    for (int base = 0; base < NN; base += 1024) {
        int idx = base + tid;
        int v = (idx < NN) ? g_cnt[idx] : 0;
        int x = v;
#pragma unroll
        for (int o = 1; o < 32; o <<= 1) {
            int y = __shfl_up_sync(0xffffffffu, x, o);
            if (lane >= o) x += y;
        }
        if (lane == 31) wsums[wid] = x;
        __syncthreads();
        if (wid == 0) {
            int s = wsums[lane];
#pragma unroll
            for (int o = 1; o < 32; o <<= 1) {
                int y = __shfl_up_sync(0xffffffffu, s, o);
                if (lane >= o) s += y;
            }
            wsums[lane] = s;
        }
        __syncthreads();
        int pref = (wid > 0) ? wsums[wid - 1] : 0;
        if (idx < NN) g_off[idx] = run + pref + x - v;
        run += wsums[31];
        __syncthreads();
    }
}
__global__ void scatter_kernel(const int* __restrict__ tgt_idx) {
    int e = blockIdx.x * blockDim.x + threadIdx.x;
    if (e < NE) {
        int slot = atomicAdd(&g_off[tgt_idx[e]], 1);
        g_perm[slot] = e;
    }
}
// warp-per-node segment sum
__global__ void agg_kernel(const float* __restrict__ edge_out) {
    int w = (blockIdx.x * blockDim.x + threadIdx.x) >> 5;
    int lane = threadIdx.x & 31;
    if (w >= NN) return;
    int end = g_off[w];
    int beg = end - g_cnt[w];
    float4 a = make_float4(0.f, 0.f, 0.f, 0.f);
    for (int j = beg; j < end; j++) {
        int e = g_perm[j];
        float4 v = __ldg((const float4*)(edge_out + (size_t)e * DD) + lane);
        a.x += v.x; a.y += v.y; a.z += v.z; a.w += v.w;
    }
    ((float4*)(g_agg + (size_t)w * DD))[lane] = a;
}

// ================= K1: fused src+tgt projection (HMMA) =================
__device__ __forceinline__ void proj_phase(char* smem, unsigned smb,
                                           const float* __restrict__ X,
                                           const float* __restrict__ W,
                                           float* __restrict__ O, int tid) {
    convert_B(smem, SM_BH, SM_BL, W, tid);
    const int wid = tid >> 5, lane = tid & 31;
    const int m0 = (wid & 3) * 32, n0 = (wid >> 2) * 32;
    const int g = lane >> 2, q = lane & 3;
    const int within = lane & 7, sub = lane >> 3;
    const int rA0 = m0 + within + ((sub & 1) << 3);
    const int rA1 = rA0 + 16;
    const int rBo = within + ((sub >> 1) << 3);

    stage_raw(smem, X, blockIdx.x * ET, NN, tid);
    __syncthreads();
    for (int t = blockIdx.x; t < NT_P; t += gridDim.x) {
        const int base = t * ET;
        cp_wait0();
        __syncthreads();
        convert_A(smem, SM_AH, SM_AL, tid);
        __syncthreads();
        const int tn = t + gridDim.x;
        if (tn < NT_P) stage_raw(smem, X, tn * ET, NN, tid);
        else cp_commit();

        float acc[2][4][4];
#pragma unroll
        for (int i = 0; i < 2; i++)
#pragma unroll
            for (int j = 0; j < 4; j++)
#pragma unroll
                for (int c = 0; c < 4; c++) acc[i][j][c] = 0.f;
        mma_tile(smb, SM_AH, SM_AL, SM_BH, SM_BL, rA0, rA1, rBo, n0, sub, acc);

        const int nR = (NN - base < ET) ? (NN - base) : ET;
#pragma unroll
        for (int mt = 0; mt < 2; mt++) {
#pragma unroll
            for (int hr = 0; hr < 2; hr++) {
                const int r = m0 + 16 * mt + 8 * hr + g;
                if (r < nR) {
                    float* o = O + (size_t)(base + r) * DD;
#pragma unroll
                    for (int j = 0; j < 4; j++) {
                        const int c = n0 + 8 * j + 2 * q;
                        *(float2*)(o + c) = make_float2(acc[mt][j][2 * hr],
                                                        acc[mt][j][2 * hr + 1]);
                    }
                }
            }
        }
    }
    __syncthreads();   // drain before caller overwrites B
}

__global__ void __launch_bounds__(NTHR, 1)
proj_kernel(const float* __restrict__ src, const float* __restrict__ tgt,
            const float* __restrict__ Ws2e, const float* __restrict__ Wt2e) {
    extern __shared__ __align__(128) char smem[];
    const unsigned smb = smem_u32(smem);
    proj_phase(smem, smb, src, Ws2e, g_srcP, threadIdx.x);
    proj_phase(smem, smb, tgt, Wt2e, g_tgtP, threadIdx.x);
}

// ================= K2: fused edge update (HMMA, no atomics) =================
__global__ void __launch_bounds__(NTHR, 1)
edge_kernel(const float* __restrict__ edge,
            const int* __restrict__ src_idx, const int* __restrict__ tgt_idx,
            const float* __restrict__ We2e,
            const float* __restrict__ ln_g, const float* __restrict__ ln_b,
            float* __restrict__ edge_out) {
    extern __shared__ __align__(128) char smem[];
    const unsigned smb = smem_u32(smem);
    const int tid = threadIdx.x;
    const int wid = tid >> 5, lane = tid & 31;

    convert_B(smem, SM_BH, SM_BL, We2e, tid);
    for (int i = tid; i < DD; i += NTHR) {
        ((float*)(smem + SM_LN))[i] = ln_g[i];
        ((float*)(smem + SM_LN))[DD + i] = ln_b[i];
    }

    const int m0 = (wid & 3) * 32, h = wid >> 2, n0 = h * 32;
    const int g = lane >> 2, q = lane & 3;
    const int within = lane & 7, sub = lane >> 3;
    const int rA0 = m0 + within + ((sub & 1) << 3);
    const int rA1 = rA0 + 16;
    const int rBo = within + ((sub >> 1) << 3);

    stage_raw(smem, edge, blockIdx.x * ET, NE, tid);
    __syncthreads();

    for (int t = blockIdx.x; t < NT_E; t += gridDim.x) {
        const int base = t * ET;
        const int nE = (NE - base < ET) ? (NE - base) : ET;
        cp_wait0();
        __syncthreads();
        convert_A(smem, SM_AH, SM_AL, tid);
        __syncthreads();
        const int tn = t + gridDim.x;
        if (tn < NT_E) stage_raw(smem, edge, tn * ET, NE, tid);
        else cp_commit();

        float acc[2][4][4];
#pragma unroll
        for (int i = 0; i < 2; i++)
#pragma unroll
            for (int j = 0; j < 4; j++)
#pragma unroll
                for (int c = 0; c < 4; c++) acc[i][j][c] = 0.f;
        mma_tile(smb, SM_AH, SM_AL, SM_BH, SM_BL, rA0, rA1, rBo, n0, sub, acc);

        // ---- epilogue part 1: u = silu(acc + srcP[s] + tgtP[t]); partial LN sums ----
#pragma unroll
        for (int mt = 0; mt < 2; mt++) {
#pragma unroll
            for (int hr = 0; hr < 2; hr++) {
                const int r = m0 + 16 * mt + 8 * hr + g;
                const int gec = base + ((r < nE) ? r : 0);
                const int si = __ldg(src_idx + gec);
                const int ti = __ldg(tgt_idx + gec);
                const float* gsp = g_srcP + (size_t)si * DD;
                const float* gtp = g_tgtP + (size_t)ti * DD;
                float s1 = 0.f, s2 = 0.f;
#pragma unroll
                for (int j = 0; j < 4; j++) {
                    const int c = n0 + 8 * j + 2 * q;
                    float2 a = __ldg((const float2*)(gsp + c));
                    float2 b = __ldg((const float2*)(gtp + c));
                    float u0 = silu(acc[mt][j][2 * hr]     + a.x + b.x);
                    float u1 = silu(acc[mt][j][2 * hr + 1] + a.y + b.y);
                    acc[mt][j][2 * hr] = u0;
                    acc[mt][j][2 * hr + 1] = u1;
                    s1 += u0 + u1;
                    s2 = fmaf(u0, u0, fmaf(u1, u1, s2));
                }
                s1 += __shfl_xor_sync(0xffffffffu, s1, 1);
                s2 += __shfl_xor_sync(0xffffffffu, s2, 1);
                s1 += __shfl_xor_sync(0xffffffffu, s1, 2);
                s2 += __shfl_xor_sync(0xffffffffu, s2, 2);
                if (q == 0)
                    ((float2*)(smem + SM_SUM))[r * 4 + h] = make_float2(s1, s2);
            }
        }
        __syncthreads();

        // ---- epilogue part 2: LN + residual (from smem hi+lo) + store ----
#pragma unroll
        for (int mt = 0; mt < 2; mt++) {
#pragma unroll
            for (int hr = 0; hr < 2; hr++) {
                const int r = m0 + 16 * mt + 8 * hr + g;
                if (r < nE) {
                    const int ge = base + r;
                    const float2* sp = (const float2*)(smem + SM_SUM) + r * 4;
                    float2 p0 = sp[0], p1 = sp[1], p2 = sp[2], p3 = sp[3];
                    const float s1 = (p0.x + p1.x) + (p2.x + p3.x);
                    const float s2 = (p0.y + p1.y) + (p2.y + p3.y);
                    const float mean = s1 * (1.0f / 128.0f);
                    const float var  = s2 * (1.0f / 128.0f) - mean * mean;
                    const float rstd = rsqrtf(var + 1e-5f);
                    float* eo = edge_out + (size_t)ge * DD;
#pragma unroll
                    for (int j = 0; j < 4; j++) {
                        const int c = n0 + 8 * j + 2 * q;
                        float2 res = smem_hilo2(smem, SM_AH, SM_AL, r, c);
                        float2 lg = *(const float2*)((const float*)(smem + SM_LN) + c);
                        float2 lb = *(const float2*)((const float*)(smem + SM_LN) + DD + c);
                        float2 o;
                        o.x = res.x + (acc[mt][j][2 * hr]     - mean) * rstd * lg.x + lb.x;
                        o.y = res.y + (acc[mt][j][2 * hr + 1] - mean) * rstd * lg.y + lb.y;
                        *(float2*)(eo + c) = o;
                    }
                }
            }
        }
    }
}

// ================= K3: fused node update (dual HMMA) =================
__global__ void __launch_bounds__(NTHR, 1)
node_kernel(const float* __restrict__ tgt,
            const float* __restrict__ We2t, const float* __restrict__ Wt2t,
            const float* __restrict__ ln_g, const float* __restrict__ ln_b,
            float* __restrict__ tgt_out) {
    extern __shared__ __align__(128) char smem[];
    const unsigned smb = smem_u32(smem);
    const int tid = threadIdx.x;
    const int wid = tid >> 5, lane = tid & 31;

    convert_B(smem, SM_N_B1H, SM_N_B1L, We2t, tid);
    convert_B(smem, SM_N_B2H, SM_N_B2L, Wt2t, tid);
    for (int i = tid; i < DD; i += NTHR) {
        ((float*)(smem + SM_LN))[i] = ln_g[i];
        ((float*)(smem + SM_LN))[DD + i] = ln_b[i];
    }

    const int m0 = (wid & 3) * 32, h = wid >> 2, n0 = h * 32;
    const int g = lane >> 2, q = lane & 3;
    const int within = lane & 7, sub = lane >> 3;
    const int rA0 = m0 + within + ((sub & 1) << 3);
    const int rA1 = rA0 + 16;
    const int rBo = within + ((sub >> 1) << 3);

    for (int t = blockIdx.x; t < NT_P; t += gridDim.x) {
        const int base = t * ET;
        const int nR = (NN - base < ET) ? (NN - base) : ET;
        __syncthreads();
        convert_A_direct(smem, SM_N_AH, SM_N_AL, g_agg, base, NN, tid);
        __syncthreads();

        float acc[2][4][4];
#pragma unroll
        for (int i = 0; i < 2; i++)
#pragma unroll
            for (int j = 0; j < 4; j++)
#pragma unroll
                for (int c = 0; c < 4; c++) acc[i][j][c] = 0.f;
        mma_tile(smb, SM_N_AH, SM_N_AL, SM_N_B1H, SM_N_B1L, rA0, rA1, rBo, n0, sub, acc);
        __syncthreads();
        convert_A_direct(smem, SM_N_AH, SM_N_AL, tgt, base, NN, tid);
        __syncthreads();
        mma_tile(smb, SM_N_AH, SM_N_AL, SM_N_B2H, SM_N_B2L, rA0, rA1, rBo, n0, sub, acc);

        // epilogue
#pragma unroll
        for (int mt = 0; mt < 2; mt++) {
#pragma unroll
            for (int hr = 0; hr < 2; hr++) {
                const int r = m0 + 16 * mt + 8 * hr + g;
                float s1 = 0.f, s2 = 0.f;
#pragma unroll
                for (int j = 0; j < 4; j++) {
                    float u0 = silu(acc[mt][j][2 * hr]);
                    float u1 = silu(acc[mt][j][2 * hr + 1]);
                    acc[mt][j][2 * hr] = u0;
                    acc[mt][j][2 * hr + 1] = u1;
                    s1 += u0 + u1;
                    s2 = fmaf(u0, u0, fmaf(u1, u1, s2));
                }
                s1 += __shfl_xor_sync(0xffffffffu, s1, 1);
                s2 += __shfl_xor_sync(0xffffffffu, s2, 1);
                s1 += __shfl_xor_sync(0xffffffffu, s1, 2);
                s2 += __shfl_xor_sync(0xffffffffu, s2, 2);
                if (q == 0)
                    ((float2*)(smem + SM_SUM))[r * 4 + h] = make_float2(s1, s2);
            }
        }
        __syncthreads();
#pragma unroll
        for (int mt = 0; mt < 2; mt++) {
#pragma unroll
            for (int hr = 0; hr < 2; hr++) {
                const int r = m0 + 16 * mt + 8 * hr + g;
                if (r < nR) {
                    const float2* sp = (const float2*)(smem + SM_SUM) + r * 4;
                    float2 p0 = sp[0], p1 = sp[1], p2 = sp[2], p3 = sp[3];
                    const float s1 = (p0.x + p1.x) + (p2.x + p3.x);
                    const float s2 = (p0.y + p1.y) + (p2.y + p3.y);
                    const float mean = s1 * (1.0f / 128.0f);
                    const float var  = s2 * (1.0f / 128.0f) - mean * mean;
                    const float rstd = rsqrtf(var + 1e-5f);
                    float* o = tgt_out + (size_t)(base + r) * DD;
#pragma unroll
                    for (int j = 0; j < 4; j++) {
                        const int c = n0 + 8 * j + 2 * q;
                        float2 res = smem_hilo2(smem, SM_N_AH, SM_N_AL, r, c);
                        float2 lg = *(const float2*)((const float*)(smem + SM_LN) + c);
                        float2 lb = *(const float2*)((const float*)(smem + SM_LN) + DD + c);
                        float2 ov;
                        ov.x = res.x + (acc[mt][j][2 * hr]     - mean) * rstd * lg.x + lb.x;
                        ov.y = res.y + (acc[mt][j][2 * hr + 1] - mean) * rstd * lg.y + lb.y;
                        *(float2*)(o + c) = ov;
                    }
                }
            }
        }
    }
}

// ---------------- launcher ----------------
extern "C" void kernel_launch(void* const* d_in, const int* in_sizes, int n_in,
                              void* d_out, int out_size) {
    (void)in_sizes; (void)n_in; (void)out_size;
    const float* src     = (const float*)d_in[0];
    const float* tgt     = (const float*)d_in[1];
    const float* edge    = (const float*)d_in[2];
    const int*   src_idx = (const int*)d_in[3];
    const int*   tgt_idx = (const int*)d_in[4];
    const float* W_s2e   = (const float*)d_in[5];
    const float* W_t2e   = (const float*)d_in[6];
    const float* W_e2e   = (const float*)d_in[7];
    const float* W_e2t   = (const float*)d_in[8];
    const float* W_t2t   = (const float*)d_in[9];
    const float* ln1_g   = (const float*)d_in[10];
    const float* ln1_b   = (const float*)d_in[11];
    const float* ln2_g   = (const float*)d_in[12];
    const float* ln2_b   = (const float*)d_in[13];

    float* edge_out = (float*)d_out;
    float* tgt_out  = (float*)d_out + (size_t)NE * DD;

    cudaFuncSetAttribute(proj_kernel, cudaFuncAttributeMaxDynamicSharedMemorySize, SMEM_PROJ);
    cudaFuncSetAttribute(edge_kernel, cudaFuncAttributeMaxDynamicSharedMemorySize, SMEM_EDGE);
    cudaFuncSetAttribute(node_kernel, cudaFuncAttributeMaxDynamicSharedMemorySize, SMEM_NODE);

    const int GP = 148;
    zero_cnt_kernel<<<(NN + 1023) / 1024, 1024>>>();                     // 1
    hist_kernel<<<(NE + 1023) / 1024, 1024>>>(tgt_idx);                  // 2
    scan_kernel<<<1, 1024>>>();                                          // 3
    scatter_kernel<<<(NE + 1023) / 1024, 1024>>>(tgt_idx);               // 4
    proj_kernel<<<GP, NTHR, SMEM_PROJ>>>(src, tgt, W_s2e, W_t2e);        // 5
    edge_kernel<<<GP, NTHR, SMEM_EDGE>>>(edge, src_idx, tgt_idx, W_e2e,
                                         ln1_g, ln1_b, edge_out);        // 6
    agg_kernel<<<(NN * 32 + 255) / 256, 256>>>(edge_out);                // 7
    node_kernel<<<GP, NTHR, SMEM_NODE>>>(tgt, W_e2t, W_t2t,
                                         ln2_g, ln2_b, tgt_out);         // 8
}

// round 16
// speedup vs baseline: 2.0667x; 1.0006x over previous
#include <cuda_runtime.h>
#include <cuda_bf16.h>

#define NN 50000
#define NE 500000
#define DD 128
#define ET 128
#define NTHR 512

#define NT_E ((NE + ET - 1) / ET)   // 3907
#define NT_P ((NN + ET - 1) / ET)   // 391

// ---- shared-memory maps (bytes) ----
// proj/edge: B hi/lo | A hi/lo | RAW fp32
#define SM_BH  0
#define SM_BL  32768
#define SM_AH  65536
#define SM_AL  98304
#define SM_RAW 131072
#define SM_LN  196608
#define SM_SUM 197632                 // 128 rows x 4 quarters x float2 = 4096 B
#define SMEM_PROJ 196608
#define SMEM_EDGE 201728
// node: B1 hi/lo | B2 hi/lo | A hi/lo (no RAW)
#define SM_N_B1H 0
#define SM_N_B1L 32768
#define SM_N_B2H 65536
#define SM_N_B2L 98304
#define SM_N_AH  131072
#define SM_N_AL  163840
#define SMEM_NODE 201728

// ---------------- device scratch ----------------
__device__ float g_srcP[(size_t)NN * DD];
__device__ float g_tgtP[(size_t)NN * DD];
__device__ float g_agg [(size_t)NN * DD];
__device__ int   g_cnt[NN];
__device__ int   g_off[NN];
__device__ int   g_perm[NE];

__device__ __forceinline__ float silu(float x) { return x * (1.0f / (1.0f + __expf(-x))); }

__device__ __forceinline__ unsigned smem_u32(const void* p) {
    unsigned a;
    asm("{ .reg .u64 t; cvta.to.shared.u64 t, %1; cvt.u32.u64 %0, t; }" : "=r"(a) : "l"(p));
    return a;
}
__device__ __forceinline__ void ldsm4(unsigned r[4], unsigned addr) {
    asm volatile("ldmatrix.sync.aligned.m8n8.x4.shared.b16 {%0,%1,%2,%3}, [%4];"
                 : "=r"(r[0]), "=r"(r[1]), "=r"(r[2]), "=r"(r[3]) : "r"(addr));
}
__device__ __forceinline__ void mma16816(float c[4], const unsigned a[4],
                                         unsigned b0, unsigned b1) {
    asm volatile("mma.sync.aligned.m16n8k16.row.col.f32.bf16.bf16.f32 "
                 "{%0,%1,%2,%3}, {%4,%5,%6,%7}, {%8,%9}, {%0,%1,%2,%3};"
                 : "+f"(c[0]), "+f"(c[1]), "+f"(c[2]), "+f"(c[3])
                 : "r"(a[0]), "r"(a[1]), "r"(a[2]), "r"(a[3]), "r"(b0), "r"(b1));
}
__device__ __forceinline__ unsigned pack_bf2(__nv_bfloat16 a, __nv_bfloat16 b) {
    __nv_bfloat162 t = __halves2bfloat162(a, b);
    return *reinterpret_cast<unsigned*>(&t);
}
__device__ __forceinline__ void cp_commit() { asm volatile("cp.async.commit_group;" ::: "memory"); }
__device__ __forceinline__ void cp_wait0()  { asm volatile("cp.async.wait_group 0;" ::: "memory"); }

// store 4 fp32 as bf16 hi/lo into swizzled tile: row pitch 256B, 16B-chunk XOR (row&7)
__device__ __forceinline__ void store_hilo(char* smem, int offH, int offL,
                                           int row, int c0, float4 v) {
    unsigned chunk = ((unsigned)c0 >> 3) ^ ((unsigned)row & 7u);
    unsigned off = (unsigned)row * 256u + chunk * 16u + ((unsigned)c0 & 7u) * 2u;
    __nv_bfloat16 hx = __float2bfloat16(v.x);
    __nv_bfloat16 hy = __float2bfloat16(v.y);
    __nv_bfloat16 hz = __float2bfloat16(v.z);
    __nv_bfloat16 hw = __float2bfloat16(v.w);
    __nv_bfloat16 lx = __float2bfloat16(v.x - __bfloat162float(hx));
    __nv_bfloat16 ly = __float2bfloat16(v.y - __bfloat162float(hy));
    __nv_bfloat16 lz = __float2bfloat16(v.z - __bfloat162float(hz));
    __nv_bfloat16 lw = __float2bfloat16(v.w - __bfloat162float(hw));
    *(uint2*)(smem + offH + off) = make_uint2(pack_bf2(hx, hy), pack_bf2(hz, hw));
    *(uint2*)(smem + offL + off) = make_uint2(pack_bf2(lx, ly), pack_bf2(lz, lw));
}

// read back exact value (hi+lo) of 2 consecutive cols from swizzled tiles
__device__ __forceinline__ float2 smem_hilo2(const char* smem, int offH, int offL, int r, int c) {
    unsigned chunk = ((unsigned)c >> 3) ^ ((unsigned)r & 7u);
    unsigned off = (unsigned)r * 256u + chunk * 16u + ((unsigned)c & 7u) * 2u;
    unsigned h = *(const unsigned*)(smem + offH + off);
    unsigned l = *(const unsigned*)(smem + offL + off);
    __nv_bfloat162 hb = *reinterpret_cast<__nv_bfloat162*>(&h);
    __nv_bfloat162 lb = *reinterpret_cast<__nv_bfloat162*>(&l);
    return make_float2(__bfloat162float(hb.x) + __bfloat162float(lb.x),
                       __bfloat162float(hb.y) + __bfloat162float(lb.y));
}

// convert B = W[n][k] (global) into bf16 hi/lo swizzled tile
__device__ __forceinline__ void convert_B(char* smem, int offH, int offL,
                                          const float* __restrict__ W, int tid) {
#pragma unroll
    for (int it = 0; it < 4096 / NTHR; it++) {
        int i = tid + it * NTHR;
        int n = i >> 5, c0 = (i & 31) << 2;
        float4 v = __ldg((const float4*)(W + (size_t)n * DD + c0));
        store_hilo(smem, offH, offL, n, c0, v);
    }
}

// cp.async stage of a raw fp32 tile (zero-fill OOB rows), commits a group
__device__ __forceinline__ void stage_raw(char* smem, const float* __restrict__ g,
                                          int base, int M, int tid) {
#pragma unroll
    for (int it = 0; it < 4096 / NTHR; it++) {
        int i = tid + it * NTHR;
        int r = i >> 5, c0 = (i & 31) << 2;
        char* dstp = smem + SM_RAW + r * 512 + c0 * 4;
        if (base + r < M) {
            unsigned dst = smem_u32(dstp);
            const float* src = g + (size_t)(base + r) * DD + c0;
            asm volatile("cp.async.cg.shared.global [%0], [%1], 16;" :: "r"(dst), "l"(src));
        } else {
            *(float4*)dstp = make_float4(0.f, 0.f, 0.f, 0.f);
        }
    }
    cp_commit();
}

// convert RAW fp32 smem tile -> bf16 hi/lo tiles
__device__ __forceinline__ void convert_A(char* smem, int offH, int offL, int tid) {
#pragma unroll
    for (int it = 0; it < 4096 / NTHR; it++) {
        int i = tid + it * NTHR;
        int r = i >> 5, c0 = (i & 31) << 2;
        float4 v = *(const float4*)(smem + SM_RAW + r * 512 + c0 * 4);
        store_hilo(smem, offH, offL, r, c0, v);
    }
}

// direct global -> bf16 hi/lo (node kernel)
__device__ __forceinline__ void convert_A_direct(char* smem, int offH, int offL,
                                                 const float* __restrict__ g,
                                                 int base, int M, int tid) {
#pragma unroll
    for (int it = 0; it < 4096 / NTHR; it++) {
        int i = tid + it * NTHR;
        int r = i >> 5, c0 = (i & 31) << 2;
        float4 v = make_float4(0.f, 0.f, 0.f, 0.f);
        if (base + r < M) v = __ldg((const float4*)(g + (size_t)(base + r) * DD + c0));
        store_hilo(smem, offH, offL, r, c0, v);
    }
}

// ---- bf16x3 HMMA: 128x128 tile, 16 warps, warp = m32 x n32 ----
// acc[mt][j][.]: row block mt (16 rows), col group j (8 cols at n0+8j)
__device__ __forceinline__ void mma_tile(unsigned smb, int offAH, int offAL,
                                         int offBH, int offBL,
                                         int rA0, int rA1, int rBo, int n0, int sub,
                                         float (&acc)[2][4][4]) {
#pragma unroll
    for (int k = 0; k < DD; k += 16) {
        const int ca = (k >> 3) + (sub >> 1);
        unsigned aH0[4], aH1[4], aL0[4], aL1[4];
        ldsm4(aH0, smb + offAH + rA0 * 256 + (((unsigned)(ca ^ (rA0 & 7))) << 4));
        ldsm4(aH1, smb + offAH + rA1 * 256 + (((unsigned)(ca ^ (rA1 & 7))) << 4));
        ldsm4(aL0, smb + offAL + rA0 * 256 + (((unsigned)(ca ^ (rA0 & 7))) << 4));
        ldsm4(aL1, smb + offAL + rA1 * 256 + (((unsigned)(ca ^ (rA1 & 7))) << 4));
        const int cb = (k >> 3) + (sub & 1);
#pragma unroll
        for (int p = 0; p < 2; p++) {
            const int rB = n0 + 16 * p + rBo;
            const unsigned boff = (unsigned)rB * 256u + (((unsigned)(cb ^ (rB & 7))) << 4);
            unsigned bH[4], bL[4];
            ldsm4(bH, smb + offBH + boff);
            mma16816(acc[0][2 * p],     aH0, bH[0], bH[1]);
            mma16816(acc[0][2 * p + 1], aH0, bH[2], bH[3]);
            mma16816(acc[1][2 * p],     aH1, bH[0], bH[1]);
            mma16816(acc[1][2 * p + 1], aH1, bH[2], bH[3]);
            mma16816(acc[0][2 * p],     aL0, bH[0], bH[1]);
            mma16816(acc[0][2 * p + 1], aL0, bH[2], bH[3]);
            mma16816(acc[1][2 * p],     aL1, bH[0], bH[1]);
            mma16816(acc[1][2 * p + 1], aL1, bH[2], bH[3]);
            ldsm4(bL, smb + offBL + boff);
            mma16816(acc[0][2 * p],     aH0, bL[0], bL[1]);
            mma16816(acc[0][2 * p + 1], aH0, bL[2], bL[3]);
            mma16816(acc[1][2 * p],     aH1, bL[0], bL[1]);
            mma16816(acc[1][2 * p + 1], aH1, bL[2], bL[3]);
        }
    }
}

// ================= sort-based segment-sum machinery =================
__global__ void zero_cnt_kernel() {
    int i = blockIdx.x * blockDim.x + threadIdx.x;
    if (i < NN) g_cnt[i] = 0;
}
__global__ void hist_kernel(const int* __restrict__ tgt_idx) {
    int e = blockIdx.x * blockDim.x + threadIdx.x;
    if (e < NE) atomicAdd(&g_cnt[tgt_idx[e]], 1);
}
__global__ void scan_kernel() {
    __shared__ int wsums[32];
    const int tid = threadIdx.x, lane = tid & 31, wid = tid >> 5;
    int run = 0;
    for (int base = 0; base < NN; base += 1024) {
        int idx = base + tid;
        int v = (idx < NN) ? g_cnt[idx] : 0;
        int x = v;
#pragma unroll
        for (int o = 1; o < 32; o <<= 1) {
            int y = __shfl_up_sync(0xffffffffu, x, o);
            if (lane >= o) x += y;
        }
        if (lane == 31) wsums[wid] = x;
        __syncthreads();
        if (wid == 0) {
            int s = wsums[lane];
#pragma unroll
            for (int o = 1; o < 32; o <<= 1) {
                int y = __shfl_up_sync(0xffffffffu, s, o);
                if (lane >= o) s += y;
            }
            wsums[lane] = s;
        }
        __syncthreads();
        int pref = (wid > 0) ? wsums[wid - 1] : 0;
        if (idx < NN) g_off[idx] = run + pref + x - v;
        run += wsums[31];
        __syncthreads();
    }
}
__global__ void scatter_kernel(const int* __restrict__ tgt_idx) {
    int e = blockIdx.x * blockDim.x + threadIdx.x;
    if (e < NE) {
        int slot = atomicAdd(&g_off[tgt_idx[e]], 1);
        g_perm[slot] = e;
    }
}
// warp-per-node segment sum
__global__ void agg_kernel(const float* __restrict__ edge_out) {
    int w = (blockIdx.x * blockDim.x + threadIdx.x) >> 5;
    int lane = threadIdx.x & 31;
    if (w >= NN) return;
    int end = g_off[w];
    int beg = end - g_cnt[w];
    float4 a = make_float4(0.f, 0.f, 0.f, 0.f);
    for (int j = beg; j < end; j++) {
        int e = g_perm[j];
        float4 v = __ldg((const float4*)(edge_out + (size_t)e * DD) + lane);
        a.x += v.x; a.y += v.y; a.z += v.z; a.w += v.w;
    }
    ((float4*)(g_agg + (size_t)w * DD))[lane] = a;
}

// ================= K1: fused src+tgt projection (HMMA) =================
__device__ __forceinline__ void proj_phase(char* smem, unsigned smb,
                                           const float* __restrict__ X,
                                           const float* __restrict__ W,
                                           float* __restrict__ O, int tid) {
    convert_B(smem, SM_BH, SM_BL, W, tid);
    const int wid = tid >> 5, lane = tid & 31;
    const int m0 = (wid & 3) * 32, n0 = (wid >> 2) * 32;
    const int g = lane >> 2, q = lane & 3;
    const int within = lane & 7, sub = lane >> 3;
    const int rA0 = m0 + within + ((sub & 1) << 3);
    const int rA1 = rA0 + 16;
    const int rBo = within + ((sub >> 1) << 3);

    stage_raw(smem, X, blockIdx.x * ET, NN, tid);
    __syncthreads();
    for (int t = blockIdx.x; t < NT_P; t += gridDim.x) {
        const int base = t * ET;
        cp_wait0();
        __syncthreads();
        convert_A(smem, SM_AH, SM_AL, tid);
        __syncthreads();
        const int tn = t + gridDim.x;
        if (tn < NT_P) stage_raw(smem, X, tn * ET, NN, tid);
        else cp_commit();

        float acc[2][4][4];
#pragma unroll
        for (int i = 0; i < 2; i++)
#pragma unroll
            for (int j = 0; j < 4; j++)
#pragma unroll
                for (int c = 0; c < 4; c++) acc[i][j][c] = 0.f;
        mma_tile(smb, SM_AH, SM_AL, SM_BH, SM_BL, rA0, rA1, rBo, n0, sub, acc);

        const int nR = (NN - base < ET) ? (NN - base) : ET;
#pragma unroll
        for (int mt = 0; mt < 2; mt++) {
#pragma unroll
            for (int hr = 0; hr < 2; hr++) {
                const int r = m0 + 16 * mt + 8 * hr + g;
                if (r < nR) {
                    float* o = O + (size_t)(base + r) * DD;
#pragma unroll
                    for (int j = 0; j < 4; j++) {
                        const int c = n0 + 8 * j + 2 * q;
                        *(float2*)(o + c) = make_float2(acc[mt][j][2 * hr],
                                                        acc[mt][j][2 * hr + 1]);
                    }
                }
            }
        }
    }
    __syncthreads();   // drain before caller overwrites B
}

__global__ void __launch_bounds__(NTHR, 1)
proj_kernel(const float* __restrict__ src, const float* __restrict__ tgt,
            const float* __restrict__ Ws2e, const float* __restrict__ Wt2e) {
    extern __shared__ __align__(128) char smem[];
    const unsigned smb = smem_u32(smem);
    proj_phase(smem, smb, src, Ws2e, g_srcP, threadIdx.x);
    proj_phase(smem, smb, tgt, Wt2e, g_tgtP, threadIdx.x);
}

// ================= K2: fused edge update (HMMA, no atomics) =================
__global__ void __launch_bounds__(NTHR, 1)
edge_kernel(const float* __restrict__ edge,
            const int* __restrict__ src_idx, const int* __restrict__ tgt_idx,
            const float* __restrict__ We2e,
            const float* __restrict__ ln_g, const float* __restrict__ ln_b,
            float* __restrict__ edge_out) {
    extern __shared__ __align__(128) char smem[];
    const unsigned smb = smem_u32(smem);
    const int tid = threadIdx.x;
    const int wid = tid >> 5, lane = tid & 31;

    convert_B(smem, SM_BH, SM_BL, We2e, tid);
    for (int i = tid; i < DD; i += NTHR) {
        ((float*)(smem + SM_LN))[i] = ln_g[i];
        ((float*)(smem + SM_LN))[DD + i] = ln_b[i];
    }

    const int m0 = (wid & 3) * 32, h = wid >> 2, n0 = h * 32;
    const int g = lane >> 2, q = lane & 3;
    const int within = lane & 7, sub = lane >> 3;
    const int rA0 = m0 + within + ((sub & 1) << 3);
    const int rA1 = rA0 + 16;
    const int rBo = within + ((sub >> 1) << 3);

    stage_raw(smem, edge, blockIdx.x * ET, NE, tid);
    __syncthreads();

    for (int t = blockIdx.x; t < NT_E; t += gridDim.x) {
        const int base = t * ET;
        const int nE = (NE - base < ET) ? (NE - base) : ET;
        cp_wait0();
        __syncthreads();
        convert_A(smem, SM_AH, SM_AL, tid);
        __syncthreads();
        const int tn = t + gridDim.x;
        if (tn < NT_E) stage_raw(smem, edge, tn * ET, NE, tid);
        else cp_commit();

        float acc[2][4][4];
#pragma unroll
        for (int i = 0; i < 2; i++)
#pragma unroll
            for (int j = 0; j < 4; j++)
#pragma unroll
                for (int c = 0; c < 4; c++) acc[i][j][c] = 0.f;
        mma_tile(smb, SM_AH, SM_AL, SM_BH, SM_BL, rA0, rA1, rBo, n0, sub, acc);

        // ---- epilogue part 1: u = silu(acc + srcP[s] + tgtP[t]); partial LN sums ----
#pragma unroll
        for (int mt = 0; mt < 2; mt++) {
#pragma unroll
            for (int hr = 0; hr < 2; hr++) {
                const int r = m0 + 16 * mt + 8 * hr + g;
                const int gec = base + ((r < nE) ? r : 0);
                const int si = __ldg(src_idx + gec);
                const int ti = __ldg(tgt_idx + gec);
                const float* gsp = g_srcP + (size_t)si * DD;
                const float* gtp = g_tgtP + (size_t)ti * DD;
                float s1 = 0.f, s2 = 0.f;
#pragma unroll
                for (int j = 0; j < 4; j++) {
                    const int c = n0 + 8 * j + 2 * q;
                    float2 a = __ldg((const float2*)(gsp + c));
                    float2 b = __ldg((const float2*)(gtp + c));
                    float u0 = silu(acc[mt][j][2 * hr]     + a.x + b.x);
                    float u1 = silu(acc[mt][j][2 * hr + 1] + a.y + b.y);
                    acc[mt][j][2 * hr] = u0;
                    acc[mt][j][2 * hr + 1] = u1;
                    s1 += u0 + u1;
                    s2 = fmaf(u0, u0, fmaf(u1, u1, s2));
                }
                s1 += __shfl_xor_sync(0xffffffffu, s1, 1);
                s2 += __shfl_xor_sync(0xffffffffu, s2, 1);
                s1 += __shfl_xor_sync(0xffffffffu, s1, 2);
                s2 += __shfl_xor_sync(0xffffffffu, s2, 2);
                if (q == 0)
                    ((float2*)(smem + SM_SUM))[r * 4 + h] = make_float2(s1, s2);
            }
        }
        __syncthreads();

        // ---- epilogue part 2: LN + residual (from smem hi+lo) + store ----
#pragma unroll
        for (int mt = 0; mt < 2; mt++) {
#pragma unroll
            for (int hr = 0; hr < 2; hr++) {
                const int r = m0 + 16 * mt + 8 * hr + g;
                if (r < nE) {
                    const int ge = base + r;
                    const float2* sp = (const float2*)(smem + SM_SUM) + r * 4;
                    float2 p0 = sp[0], p1 = sp[1], p2 = sp[2], p3 = sp[3];
                    const float s1 = (p0.x + p1.x) + (p2.x + p3.x);
                    const float s2 = (p0.y + p1.y) + (p2.y + p3.y);
                    const float mean = s1 * (1.0f / 128.0f);
                    const float var  = s2 * (1.0f / 128.0f) - mean * mean;
                    const float rstd = rsqrtf(var + 1e-5f);
                    float* eo = edge_out + (size_t)ge * DD;
#pragma unroll
                    for (int j = 0; j < 4; j++) {
                        const int c = n0 + 8 * j + 2 * q;
                        float2 res = smem_hilo2(smem, SM_AH, SM_AL, r, c);
                        float2 lg = *(const float2*)((const float*)(smem + SM_LN) + c);
                        float2 lb = *(const float2*)((const float*)(smem + SM_LN) + DD + c);
                        float2 o;
                        o.x = res.x + (acc[mt][j][2 * hr]     - mean) * rstd * lg.x + lb.x;
                        o.y = res.y + (acc[mt][j][2 * hr + 1] - mean) * rstd * lg.y + lb.y;
                        *(float2*)(eo + c) = o;
                    }
                }
            }
        }
    }
}

// ================= K3: fused node update (dual HMMA) =================
__global__ void __launch_bounds__(NTHR, 1)
node_kernel(const float* __restrict__ tgt,
            const float* __restrict__ We2t, const float* __restrict__ Wt2t,
            const float* __restrict__ ln_g, const float* __restrict__ ln_b,
            float* __restrict__ tgt_out) {
    extern __shared__ __align__(128) char smem[];
    const unsigned smb = smem_u32(smem);
    const int tid = threadIdx.x;
    const int wid = tid >> 5, lane = tid & 31;

    convert_B(smem, SM_N_B1H, SM_N_B1L, We2t, tid);
    convert_B(smem, SM_N_B2H, SM_N_B2L, Wt2t, tid);
    for (int i = tid; i < DD; i += NTHR) {
        ((float*)(smem + SM_LN))[i] = ln_g[i];
        ((float*)(smem + SM_LN))[DD + i] = ln_b[i];
    }

    const int m0 = (wid & 3) * 32, h = wid >> 2, n0 = h * 32;
    const int g = lane >> 2, q = lane & 3;
    const int within = lane & 7, sub = lane >> 3;
    const int rA0 = m0 + within + ((sub & 1) << 3);
    const int rA1 = rA0 + 16;
    const int rBo = within + ((sub >> 1) << 3);

    for (int t = blockIdx.x; t < NT_P; t += gridDim.x) {
        const int base = t * ET;
        const int nR = (NN - base < ET) ? (NN - base) : ET;
        __syncthreads();
        convert_A_direct(smem, SM_N_AH, SM_N_AL, g_agg, base, NN, tid);
        __syncthreads();

        float acc[2][4][4];
#pragma unroll
        for (int i = 0; i < 2; i++)
#pragma unroll
            for (int j = 0; j < 4; j++)
#pragma unroll
                for (int c = 0; c < 4; c++) acc[i][j][c] = 0.f;
        mma_tile(smb, SM_N_AH, SM_N_AL, SM_N_B1H, SM_N_B1L, rA0, rA1, rBo, n0, sub, acc);
        __syncthreads();
        convert_A_direct(smem, SM_N_AH, SM_N_AL, tgt, base, NN, tid);
        __syncthreads();
        mma_tile(smb, SM_N_AH, SM_N_AL, SM_N_B2H, SM_N_B2L, rA0, rA1, rBo, n0, sub, acc);

        // epilogue
#pragma unroll
        for (int mt = 0; mt < 2; mt++) {
#pragma unroll
            for (int hr = 0; hr < 2; hr++) {
                const int r = m0 + 16 * mt + 8 * hr + g;
                float s1 = 0.f, s2 = 0.f;
#pragma unroll
                for (int j = 0; j < 4; j++) {
                    float u0 = silu(acc[mt][j][2 * hr]);
                    float u1 = silu(acc[mt][j][2 * hr + 1]);
                    acc[mt][j][2 * hr] = u0;
                    acc[mt][j][2 * hr + 1] = u1;
                    s1 += u0 + u1;
                    s2 = fmaf(u0, u0, fmaf(u1, u1, s2));
                }
                s1 += __shfl_xor_sync(0xffffffffu, s1, 1);
                s2 += __shfl_xor_sync(0xffffffffu, s2, 1);
                s1 += __shfl_xor_sync(0xffffffffu, s1, 2);
                s2 += __shfl_xor_sync(0xffffffffu, s2, 2);
                if (q == 0)
                    ((float2*)(smem + SM_SUM))[r * 4 + h] = make_float2(s1, s2);
            }
        }
        __syncthreads();
#pragma unroll
        for (int mt = 0; mt < 2; mt++) {
#pragma unroll
            for (int hr = 0; hr < 2; hr++) {
                const int r = m0 + 16 * mt + 8 * hr + g;
                if (r < nR) {
                    const float2* sp = (const float2*)(smem + SM_SUM) + r * 4;
                    float2 p0 = sp[0], p1 = sp[1], p2 = sp[2], p3 = sp[3];
                    const float s1 = (p0.x + p1.x) + (p2.x + p3.x);
                    const float s2 = (p0.y + p1.y) + (p2.y + p3.y);
                    const float mean = s1 * (1.0f / 128.0f);
                    const float var  = s2 * (1.0f / 128.0f) - mean * mean;
                    const float rstd = rsqrtf(var + 1e-5f);
                    float* o = tgt_out + (size_t)(base + r) * DD;
#pragma unroll
                    for (int j = 0; j < 4; j++) {
                        const int c = n0 + 8 * j + 2 * q;
                        float2 res = smem_hilo2(smem, SM_N_AH, SM_N_AL, r, c);
                        float2 lg = *(const float2*)((const float*)(smem + SM_LN) + c);
                        float2 lb = *(const float2*)((const float*)(smem + SM_LN) + DD + c);
                        float2 ov;
                        ov.x = res.x + (acc[mt][j][2 * hr]     - mean) * rstd * lg.x + lb.x;
                        ov.y = res.y + (acc[mt][j][2 * hr + 1] - mean) * rstd * lg.y + lb.y;
                        *(float2*)(o + c) = ov;
                    }
                }
            }
        }
    }
}

// ---------------- launcher ----------------
extern "C" void kernel_launch(void* const* d_in, const int* in_sizes, int n_in,
                              void* d_out, int out_size) {
    (void)in_sizes; (void)n_in; (void)out_size;
    const float* src     = (const float*)d_in[0];
    const float* tgt     = (const float*)d_in[1];
    const float* edge    = (const float*)d_in[2];
    const int*   src_idx = (const int*)d_in[3];
    const int*   tgt_idx = (const int*)d_in[4];
    const float* W_s2e   = (const float*)d_in[5];
    const float* W_t2e   = (const float*)d_in[6];
    const float* W_e2e   = (const float*)d_in[7];
    const float* W_e2t   = (const float*)d_in[8];
    const float* W_t2t   = (const float*)d_in[9];
    const float* ln1_g   = (const float*)d_in[10];
    const float* ln1_b   = (const float*)d_in[11];
    const float* ln2_g   = (const float*)d_in[12];
    const float* ln2_b   = (const float*)d_in[13];

    float* edge_out = (float*)d_out;
    float* tgt_out  = (float*)d_out + (size_t)NE * DD;

    cudaFuncSetAttribute(proj_kernel, cudaFuncAttributeMaxDynamicSharedMemorySize, SMEM_PROJ);
    cudaFuncSetAttribute(edge_kernel, cudaFuncAttributeMaxDynamicSharedMemorySize, SMEM_EDGE);
    cudaFuncSetAttribute(node_kernel, cudaFuncAttributeMaxDynamicSharedMemorySize, SMEM_NODE);

    const int GP = 148;
    zero_cnt_kernel<<<(NN + 1023) / 1024, 1024>>>();                     // 1
    hist_kernel<<<(NE + 1023) / 1024, 1024>>>(tgt_idx);                  // 2
    scan_kernel<<<1, 1024>>>();                                          // 3
    scatter_kernel<<<(NE + 1023) / 1024, 1024>>>(tgt_idx);               // 4
    proj_kernel<<<GP, NTHR, SMEM_PROJ>>>(src, tgt, W_s2e, W_t2e);        // 5
    edge_kernel<<<GP, NTHR, SMEM_EDGE>>>(edge, src_idx, tgt_idx, W_e2e,
                                         ln1_g, ln1_b, edge_out);        // 6
    agg_kernel<<<(NN * 32 + 255) / 256, 256>>>(edge_out);                // 7
    node_kernel<<<GP, NTHR, SMEM_NODE>>>(tgt, W_e2t, W_t2t,
                                         ln2_g, ln2_b, tgt_out);         // 8
}